// round 2
// baseline (speedup 1.0000x reference)
#include <cuda_runtime.h>

// ---------------- fixed problem shapes ----------------
#define NN      50000
#define EE      800000
#define ELOOP   850000        // EE + NN self loops
#define GG      64
#define FIN     128
#define HIDD    64
#define HEADS   4
#define C1      256           // HEADS*HIDD
#define CLIN    32
#define MET     128
#define FUSED_IN 224          // HIDD + CLIN + MET

// ---------------- device scratch (no allocs allowed) ----------------
__device__ float g_h1  [(size_t)NN * C1];     // x @ W1
__device__ float g_out1[(size_t)NN * C1];     // layer1 aggregate (then +b1, relu)
__device__ float g_h2  [(size_t)NN * HIDD];   // out1 @ W2
__device__ float g_out2[(size_t)NN * HIDD];   // layer2 aggregate
__device__ float g_als1[NN * HEADS];
__device__ float g_ald1[NN * HEADS];
__device__ float g_als2[NN];
__device__ float g_ald2[NN];
__device__ float g_ex1 [(size_t)ELOOP * HEADS];
__device__ float g_ex2 [ELOOP];
__device__ float g_den1[NN * HEADS];
__device__ float g_den2[NN];
__device__ float g_sums[GG * HIDD];
__device__ float g_cnt [GG];
__device__ float g_scal[8];   // [0]=sum(edge_attr), [1..4]=ce1[h], [5]=ce2

// ---------------- zero scratch ----------------
__global__ void zero_all_kernel() {
    size_t stride = (size_t)gridDim.x * blockDim.x;
    size_t i0 = (size_t)blockIdx.x * blockDim.x + threadIdx.x;
    for (size_t i = i0; i < (size_t)NN * C1;   i += stride) g_out1[i] = 0.f;
    for (size_t i = i0; i < (size_t)NN * HIDD; i += stride) g_out2[i] = 0.f;
    for (size_t i = i0; i < (size_t)NN * HEADS;i += stride) g_den1[i] = 0.f;
    for (size_t i = i0; i < (size_t)NN;        i += stride) g_den2[i] = 0.f;
    for (size_t i = i0; i < (size_t)GG * HIDD; i += stride) g_sums[i] = 0.f;
    if (i0 < GG) g_cnt[i0] = 0.f;
    if (i0 < 8)  g_scal[i0] = 0.f;
}

// ---------------- mean(edge_attr) : store the SUM in g_scal[0] ----------------
__global__ void mean_ea_kernel(const float* __restrict__ ea) {
    __shared__ float sh[8];
    size_t stride = (size_t)gridDim.x * blockDim.x;
    float s = 0.f;
    for (size_t i = (size_t)blockIdx.x * blockDim.x + threadIdx.x; i < EE; i += stride)
        s += ea[i];
    for (int o = 16; o; o >>= 1) s += __shfl_xor_sync(0xffffffffu, s, o);
    if ((threadIdx.x & 31) == 0) sh[threadIdx.x >> 5] = s;
    __syncthreads();
    if (threadIdx.x < 8) {
        float v = sh[threadIdx.x];
        for (int o = 4; o; o >>= 1) v += __shfl_xor_sync(0xffu, v, o);
        if (threadIdx.x == 0) atomicAdd(&g_scal[0], v);
    }
}

// ---------------- ce1[h] = sum_c We1[h*64+c]*ae1[h*64+c] ; ce2 = We2 . ae2 ----------------
__global__ void ce_kernel(const float* __restrict__ We1, const float* __restrict__ ae1,
                          const float* __restrict__ We2, const float* __restrict__ ae2) {
    int t = threadIdx.x;                       // 256 threads
    atomicAdd(&g_scal[1 + (t >> 6)], We1[t] * ae1[t]);
    if (t < 64) atomicAdd(&g_scal[5], We2[t] * ae2[t]);
}

// ---------------- SGEMM: C[M,Ncol] = A[M,K] x B[K,Ncol], row major ----------------
// 64x64 block tile, BK=16, 4x4 per thread, 256 threads.
__device__ __forceinline__ void gemm_body(const float* __restrict__ A,
                                          const float* __restrict__ B,
                                          float* __restrict__ C,
                                          int M, int Ncol, int K) {
    __shared__ float As[16][65];
    __shared__ float Bs[16][64];
    int tid = threadIdx.x;
    int tx = tid & 15, ty = tid >> 4;
    int m0 = blockIdx.y * 64, n0 = blockIdx.x * 64;
    int ar = tid >> 2, ac = (tid & 3) * 4;     // A tile coords
    int br = tid >> 4, bc = (tid & 15) * 4;    // B tile coords
    float acc[4][4];
#pragma unroll
    for (int i = 0; i < 4; i++)
#pragma unroll
        for (int j = 0; j < 4; j++) acc[i][j] = 0.f;

    for (int k0 = 0; k0 < K; k0 += 16) {
        float4 av = make_float4(0.f, 0.f, 0.f, 0.f);
        if (m0 + ar < M)
            av = *(const float4*)(A + (size_t)(m0 + ar) * K + k0 + ac);
        float4 bv = *(const float4*)(B + (size_t)(k0 + br) * Ncol + n0 + bc);
        __syncthreads();
        As[ac + 0][ar] = av.x; As[ac + 1][ar] = av.y;
        As[ac + 2][ar] = av.z; As[ac + 3][ar] = av.w;
        *(float4*)&Bs[br][bc] = bv;
        __syncthreads();
#pragma unroll
        for (int kk = 0; kk < 16; kk++) {
            float a0 = As[kk][ty * 4 + 0], a1 = As[kk][ty * 4 + 1];
            float a2 = As[kk][ty * 4 + 2], a3 = As[kk][ty * 4 + 3];
            float4 b = *(float4*)&Bs[kk][tx * 4];
            acc[0][0] += a0 * b.x; acc[0][1] += a0 * b.y; acc[0][2] += a0 * b.z; acc[0][3] += a0 * b.w;
            acc[1][0] += a1 * b.x; acc[1][1] += a1 * b.y; acc[1][2] += a1 * b.z; acc[1][3] += a1 * b.w;
            acc[2][0] += a2 * b.x; acc[2][1] += a2 * b.y; acc[2][2] += a2 * b.z; acc[2][3] += a2 * b.w;
            acc[3][0] += a3 * b.x; acc[3][1] += a3 * b.y; acc[3][2] += a3 * b.z; acc[3][3] += a3 * b.w;
        }
    }
#pragma unroll
    for (int i = 0; i < 4; i++) {
        int row = m0 + ty * 4 + i;
        if (row < M)
            *(float4*)(C + (size_t)row * Ncol + n0 + tx * 4) =
                make_float4(acc[i][0], acc[i][1], acc[i][2], acc[i][3]);
    }
}

__global__ void gemm1_kernel(const float* __restrict__ x, const float* __restrict__ W1) {
    gemm_body(x, W1, g_h1, NN, C1, FIN);
}
__global__ void gemm2_kernel(const float* __restrict__ W2) {
    gemm_body(g_out1, W2, g_h2, NN, HIDD, C1);
}

// ---------------- per-node attention logits, layer 1 (warp per node) ----------------
__global__ void logits1_kernel(const float* __restrict__ as1, const float* __restrict__ ad1) {
    int w = (blockIdx.x * blockDim.x + threadIdx.x) >> 5;
    int lane = threadIdx.x & 31;
    if (w >= NN) return;
    const float4* hp = (const float4*)(g_h1 + (size_t)w * C1);
    const float4* sp = (const float4*)as1;
    const float4* dp = (const float4*)ad1;
    float4 h0 = hp[lane * 2], h1v = hp[lane * 2 + 1];
    float4 s0 = sp[lane * 2], s1  = sp[lane * 2 + 1];
    float4 d0 = dp[lane * 2], d1  = dp[lane * 2 + 1];
    float ss = h0.x*s0.x + h0.y*s0.y + h0.z*s0.z + h0.w*s0.w
             + h1v.x*s1.x + h1v.y*s1.y + h1v.z*s1.z + h1v.w*s1.w;
    float dd = h0.x*d0.x + h0.y*d0.y + h0.z*d0.z + h0.w*d0.w
             + h1v.x*d1.x + h1v.y*d1.y + h1v.z*d1.z + h1v.w*d1.w;
    for (int o = 4; o; o >>= 1) {
        ss += __shfl_down_sync(0xffffffffu, ss, o, 8);
        dd += __shfl_down_sync(0xffffffffu, dd, o, 8);
    }
    if ((lane & 7) == 0) {
        g_als1[w * 4 + (lane >> 3)] = ss;
        g_ald1[w * 4 + (lane >> 3)] = dd;
    }
}

// ---------------- layer-1 edge pass A: exp(leakyrelu(logit)) + denominator ----------------
__global__ void edgeA1_kernel(const int* __restrict__ ei, const float* __restrict__ ea) {
    int e = blockIdx.x * blockDim.x + threadIdx.x;
    if (e >= ELOOP) return;
    int s, d; float att;
    if (e < EE) { s = ei[e]; d = ei[EE + e]; att = ea[e]; }
    else        { s = d = e - EE; att = g_scal[0] * (1.0f / EE); }
    float4 as = *(const float4*)(g_als1 + s * 4);
    float4 ad = *(const float4*)(g_ald1 + d * 4);
    float z0 = as.x + ad.x + att * g_scal[1];
    float z1 = as.y + ad.y + att * g_scal[2];
    float z2 = as.z + ad.z + att * g_scal[3];
    float z3 = as.w + ad.w + att * g_scal[4];
    z0 = z0 > 0.f ? z0 : 0.2f * z0;
    z1 = z1 > 0.f ? z1 : 0.2f * z1;
    z2 = z2 > 0.f ? z2 : 0.2f * z2;
    z3 = z3 > 0.f ? z3 : 0.2f * z3;
    float4 ex = make_float4(expf(z0), expf(z1), expf(z2), expf(z3));
    *(float4*)(g_ex1 + (size_t)e * 4) = ex;
    atomicAdd(&g_den1[d * 4 + 0], ex.x);
    atomicAdd(&g_den1[d * 4 + 1], ex.y);
    atomicAdd(&g_den1[d * 4 + 2], ex.z);
    atomicAdd(&g_den1[d * 4 + 3], ex.w);
}

// ---------------- layer-1 edge pass B: out[dst] += a * h[src]  (warp per edge) ----------------
__global__ void edgeB1_kernel(const int* __restrict__ ei) {
    int w = (blockIdx.x * blockDim.x + threadIdx.x) >> 5;
    int lane = threadIdx.x & 31;
    if (w >= ELOOP) return;
    int s, d;
    if (w < EE) { s = ei[w]; d = ei[EE + w]; }
    else        { s = d = w - EE; }
    int h = lane >> 3;     // 8 lanes per head (64 floats per head)
    float a = g_ex1[(size_t)w * 4 + h] / (g_den1[d * 4 + h] + 1e-16f);
    const float4* sp = (const float4*)(g_h1 + (size_t)s * C1);
    float* op = g_out1 + (size_t)d * C1;
    float4 v0 = sp[lane * 2], v1 = sp[lane * 2 + 1];
    int base = lane * 8;
    atomicAdd(op + base + 0, v0.x * a);
    atomicAdd(op + base + 1, v0.y * a);
    atomicAdd(op + base + 2, v0.z * a);
    atomicAdd(op + base + 3, v0.w * a);
    atomicAdd(op + base + 4, v1.x * a);
    atomicAdd(op + base + 5, v1.y * a);
    atomicAdd(op + base + 6, v1.z * a);
    atomicAdd(op + base + 7, v1.w * a);
}

// ---------------- bias + relu layer1 (in place on g_out1) ----------------
__global__ void bias_relu1_kernel(const float* __restrict__ b1) {
    size_t i = (size_t)blockIdx.x * blockDim.x + threadIdx.x;
    if (i >= (size_t)NN * C1) return;
    float v = g_out1[i] + b1[i & 255];
    g_out1[i] = v > 0.f ? v : 0.f;
}

// ---------------- per-node logits, layer 2 (warp per node) ----------------
__global__ void logits2_kernel(const float* __restrict__ as2, const float* __restrict__ ad2) {
    int w = (blockIdx.x * blockDim.x + threadIdx.x) >> 5;
    int lane = threadIdx.x & 31;
    if (w >= NN) return;
    float2 v = ((const float2*)(g_h2 + (size_t)w * HIDD))[lane];
    float2 s = ((const float2*)as2)[lane];
    float2 dv = ((const float2*)ad2)[lane];
    float ss = v.x * s.x + v.y * s.y;
    float dd = v.x * dv.x + v.y * dv.y;
    for (int o = 16; o; o >>= 1) {
        ss += __shfl_xor_sync(0xffffffffu, ss, o);
        dd += __shfl_xor_sync(0xffffffffu, dd, o);
    }
    if (lane == 0) { g_als2[w] = ss; g_ald2[w] = dd; }
}

// ---------------- layer-2 edge pass A ----------------
__global__ void edgeA2_kernel(const int* __restrict__ ei, const float* __restrict__ ea) {
    int e = blockIdx.x * blockDim.x + threadIdx.x;
    if (e >= ELOOP) return;
    int s, d; float att;
    if (e < EE) { s = ei[e]; d = ei[EE + e]; att = ea[e]; }
    else        { s = d = e - EE; att = g_scal[0] * (1.0f / EE); }
    float z = g_als2[s] + g_ald2[d] + att * g_scal[5];
    z = z > 0.f ? z : 0.2f * z;
    float ex = expf(z);
    g_ex2[e] = ex;
    atomicAdd(&g_den2[d], ex);
}

// ---------------- layer-2 edge pass B (16 lanes per edge, float4 each) ----------------
__global__ void edgeB2_kernel(const int* __restrict__ ei) {
    int t = blockIdx.x * blockDim.x + threadIdx.x;
    int e = t >> 4;
    if (e >= ELOOP) return;
    int sub = t & 15;
    int s, d;
    if (e < EE) { s = ei[e]; d = ei[EE + e]; }
    else        { s = d = e - EE; }
    float a = g_ex2[e] / (g_den2[d] + 1e-16f);
    float4 v = ((const float4*)(g_h2 + (size_t)s * HIDD))[sub];
    float* op = g_out2 + (size_t)d * HIDD + sub * 4;
    atomicAdd(op + 0, v.x * a);
    atomicAdd(op + 1, v.y * a);
    atomicAdd(op + 2, v.z * a);
    atomicAdd(op + 3, v.w * a);
}

// ---------------- LayerNorm + global mean pool accumulate (warp per node) ----------------
__global__ void ln_pool_kernel(const float* __restrict__ b2,
                               const float* __restrict__ lng, const float* __restrict__ lnb,
                               const int* __restrict__ batch) {
    int n = (blockIdx.x * blockDim.x + threadIdx.x) >> 5;
    int lane = threadIdx.x & 31;
    if (n >= NN) return;
    float2 v = ((const float2*)(g_out2 + (size_t)n * HIDD))[lane];
    v.x += b2[lane * 2]; v.y += b2[lane * 2 + 1];
    float s = v.x + v.y;
    for (int o = 16; o; o >>= 1) s += __shfl_xor_sync(0xffffffffu, s, o);
    float mu = s * (1.0f / 64.0f);
    float dx = v.x - mu, dy = v.y - mu;
    float q = dx * dx + dy * dy;
    for (int o = 16; o; o >>= 1) q += __shfl_xor_sync(0xffffffffu, q, o);
    float r = rsqrtf(q * (1.0f / 64.0f) + 1e-5f);
    float y0 = dx * r * lng[lane * 2]     + lnb[lane * 2];
    float y1 = dy * r * lng[lane * 2 + 1] + lnb[lane * 2 + 1];
    int g = batch[n];
    atomicAdd(&g_sums[g * 64 + lane * 2],     y0);
    atomicAdd(&g_sums[g * 64 + lane * 2 + 1], y1);
    if (lane == 0) atomicAdd(&g_cnt[g], 1.0f);
}

// ---------------- per-graph MLP head (block per graph, 64 threads) ----------------
__global__ void mlp_kernel(const float* __restrict__ clin, const float* __restrict__ met,
                           const float* __restrict__ Wf1, const float* __restrict__ bf1,
                           const float* __restrict__ Wf2, const float* __restrict__ bf2,
                           const float* __restrict__ Wr,  const float* __restrict__ br,
                           float* __restrict__ out) {
    int g = blockIdx.x, t = threadIdx.x;   // 64 threads
    __shared__ float fused[FUSED_IN];
    __shared__ float l1[64];
    __shared__ float l2[32];
    float cnt = g_cnt[g]; cnt = cnt > 1.f ? cnt : 1.f;
    float e = g_sums[g * 64 + t] / cnt;
    fused[t] = e;
    out[GG + g * 64 + t] = e;              // graph_embedding at offset 64
    if (t < 32) fused[64 + t] = clin[g * 32 + t];
    fused[96 + t]  = met[g * 128 + t];
    fused[160 + t] = met[g * 128 + 64 + t];
    __syncthreads();
    float acc = bf1[t];
#pragma unroll 8
    for (int k = 0; k < FUSED_IN; k++) acc += fused[k] * Wf1[k * 64 + t];
    l1[t] = acc > 0.f ? acc : 0.f;
    __syncthreads();
    if (t < 32) {
        float a2 = bf2[t];
#pragma unroll 8
        for (int j = 0; j < 64; j++) a2 += l1[j] * Wf2[j * 32 + t];
        a2 = a2 > 0.f ? a2 : 0.f;
        l2[t] = a2;
        out[GG + GG * 64 + g * 32 + t] = a2;   // latent at offset 64 + 4096
    }
    __syncthreads();
    if (t == 0) {
        float r = br[0];
#pragma unroll
        for (int j = 0; j < 32; j++) r += l2[j] * Wr[j];
        out[g] = r;                        // risk at offset 0
    }
}

// ---------------- launch ----------------
extern "C" void kernel_launch(void* const* d_in, const int* in_sizes, int n_in,
                              void* d_out, int out_size) {
    const float* x    = (const float*)d_in[0];
    const int*   ei   = (const int*)d_in[1];
    const float* ea   = (const float*)d_in[2];
    const int*   bat  = (const int*)d_in[3];
    const float* clin = (const float*)d_in[4];
    const float* met  = (const float*)d_in[5];
    const float* W1   = (const float*)d_in[6];
    const float* as1  = (const float*)d_in[7];
    const float* ad1  = (const float*)d_in[8];
    const float* ae1  = (const float*)d_in[9];
    const float* We1  = (const float*)d_in[10];
    const float* b1   = (const float*)d_in[11];
    const float* W2   = (const float*)d_in[12];
    const float* as2  = (const float*)d_in[13];
    const float* ad2  = (const float*)d_in[14];
    const float* ae2  = (const float*)d_in[15];
    const float* We2  = (const float*)d_in[16];
    const float* b2   = (const float*)d_in[17];
    const float* lng  = (const float*)d_in[18];
    const float* lnb  = (const float*)d_in[19];
    const float* Wf1  = (const float*)d_in[20];
    const float* bf1  = (const float*)d_in[21];
    const float* Wf2  = (const float*)d_in[22];
    const float* bf2  = (const float*)d_in[23];
    const float* Wr   = (const float*)d_in[24];
    const float* br   = (const float*)d_in[25];
    float* out = (float*)d_out;

    zero_all_kernel<<<2048, 256>>>();
    mean_ea_kernel<<<512, 256>>>(ea);
    ce_kernel<<<1, 256>>>(We1, ae1, We2, ae2);

    // layer 1
    gemm1_kernel<<<dim3(C1 / 64, (NN + 63) / 64), 256>>>(x, W1);
    logits1_kernel<<<(NN * 32 + 255) / 256, 256>>>(as1, ad1);
    edgeA1_kernel<<<(ELOOP + 255) / 256, 256>>>(ei, ea);
    edgeB1_kernel<<<(ELOOP * 32 + 255) / 256, 256>>>(ei);
    bias_relu1_kernel<<<(NN * C1 + 255) / 256, 256>>>(b1);

    // layer 2
    gemm2_kernel<<<dim3(HIDD / 64, (NN + 63) / 64), 256>>>(W2);
    logits2_kernel<<<(NN * 32 + 255) / 256, 256>>>(as2, ad2);
    edgeA2_kernel<<<(ELOOP + 255) / 256, 256>>>(ei, ea);
    edgeB2_kernel<<<(ELOOP * 16 + 255) / 256, 256>>>(ei);

    // layernorm + pool + head
    ln_pool_kernel<<<(NN * 32 + 255) / 256, 256>>>(b2, lng, lnb, bat);
    mlp_kernel<<<GG, 64>>>(clin, met, Wf1, bf1, Wf2, bf2, Wr, br, out);
}

// round 3
// speedup vs baseline: 3.0484x; 3.0484x over previous
#include <cuda_runtime.h>

// ---------------- fixed problem shapes ----------------
#define NN      50000
#define EE      800000
#define ELOOP   850000        // EE + NN self loops
#define GG      64
#define FIN     128
#define HIDD    64
#define HEADS   4
#define C1      256           // HEADS*HIDD
#define CLIN    32
#define MET     128
#define FUSED_IN 224          // HIDD + CLIN + MET

// ---------------- device scratch (no allocs allowed) ----------------
__device__ float g_h1  [(size_t)NN * C1];     // x @ W1
__device__ float g_out1[(size_t)NN * C1];     // layer1 output (post bias+relu)
__device__ float g_h2  [(size_t)NN * HIDD];   // out1 @ W2
__device__ float g_als1[NN * HEADS];
__device__ float g_ald1[NN * HEADS];
__device__ float g_als2[NN];
__device__ float g_ald2[NN];
__device__ float g_ex1 [(size_t)ELOOP * HEADS];
__device__ float g_ex2 [ELOOP];
__device__ float g_sums[GG * HIDD];
__device__ float g_cnt [GG];
__device__ float g_scal[8];     // [0]=sum(edge_attr), [1..4]=ce1[h], [5]=ce2
// CSR by destination
__device__ int  g_row [NN + 1];
__device__ int  g_cur [NN];     // doubles as deg (hist) then write cursor
__device__ int2 g_elist[ELOOP]; // (src, edge_id) sorted by dst

// ---------------- zero the small scratch ----------------
__global__ void zero_small_kernel() {
    int i = blockIdx.x * blockDim.x + threadIdx.x;
    if (i < NN) g_cur[i] = 0;
    if (i < GG * HIDD) g_sums[i] = 0.f;
    if (i < GG) g_cnt[i] = 0.f;
    if (i < 8)  g_scal[i] = 0.f;
}

// ---------------- mean(edge_attr): SUM into g_scal[0] ----------------
__global__ void mean_ea_kernel(const float* __restrict__ ea) {
    __shared__ float sh[8];
    size_t stride = (size_t)gridDim.x * blockDim.x;
    float s = 0.f;
    for (size_t i = (size_t)blockIdx.x * blockDim.x + threadIdx.x; i < EE; i += stride)
        s += ea[i];
    for (int o = 16; o; o >>= 1) s += __shfl_xor_sync(0xffffffffu, s, o);
    if ((threadIdx.x & 31) == 0) sh[threadIdx.x >> 5] = s;
    __syncthreads();
    if (threadIdx.x < 8) {
        float v = sh[threadIdx.x];
        for (int o = 4; o; o >>= 1) v += __shfl_xor_sync(0xffu, v, o);
        if (threadIdx.x == 0) atomicAdd(&g_scal[0], v);
    }
}

// ---------------- ce1[h] = We1.ae1 per head ; ce2 = We2.ae2 ----------------
__global__ void ce_kernel(const float* __restrict__ We1, const float* __restrict__ ae1,
                          const float* __restrict__ We2, const float* __restrict__ ae2) {
    int t = threadIdx.x;                       // 256 threads
    atomicAdd(&g_scal[1 + (t >> 6)], We1[t] * ae1[t]);
    if (t < 64) atomicAdd(&g_scal[5], We2[t] * ae2[t]);
}

// ---------------- CSR build: histogram of dst ----------------
__global__ void hist_kernel(const int* __restrict__ ei) {
    int e = blockIdx.x * blockDim.x + threadIdx.x;
    if (e >= ELOOP) return;
    int d = (e < EE) ? ei[EE + e] : (e - EE);
    atomicAdd(&g_cur[d], 1);
}

// ---------------- CSR build: exclusive scan (single block, 1024 thr) ----------------
#define CHUNK 49   // 1024*49 = 50176 >= NN
__global__ void scan_kernel() {
    __shared__ int ps[1024];
    int t = threadIdx.x;
    int base = t * CHUNK;
    int s = 0;
    for (int i = 0; i < CHUNK; i++) {
        int idx = base + i;
        if (idx < NN) s += g_cur[idx];
    }
    ps[t] = s;
    __syncthreads();
    for (int off = 1; off < 1024; off <<= 1) {
        int v = (t >= off) ? ps[t - off] : 0;
        __syncthreads();
        ps[t] += v;
        __syncthreads();
    }
    int run = ps[t] - s;   // exclusive prefix of this chunk
    for (int i = 0; i < CHUNK; i++) {
        int idx = base + i;
        if (idx < NN) {
            int d = g_cur[idx];
            g_row[idx] = run;
            g_cur[idx] = run;   // reset cursor to start offset
            run += d;
        }
    }
    if (t == 0) g_row[NN] = ELOOP;
}

// ---------------- CSR build: scatter edge ids ----------------
__global__ void scatter_kernel(const int* __restrict__ ei) {
    int e = blockIdx.x * blockDim.x + threadIdx.x;
    if (e >= ELOOP) return;
    int s, d;
    if (e < EE) { s = ei[e]; d = ei[EE + e]; }
    else        { s = d = e - EE; }
    int pos = atomicAdd(&g_cur[d], 1);
    g_elist[pos] = make_int2(s, e);
}

// ---------------- SGEMM: C[M,Ncol] = A[M,K] x B[K,Ncol], row major ----------------
__device__ __forceinline__ void gemm_body(const float* __restrict__ A,
                                          const float* __restrict__ B,
                                          float* __restrict__ C,
                                          int M, int Ncol, int K) {
    __shared__ float As[16][65];
    __shared__ float Bs[16][64];
    int tid = threadIdx.x;
    int tx = tid & 15, ty = tid >> 4;
    int m0 = blockIdx.y * 64, n0 = blockIdx.x * 64;
    int ar = tid >> 2, ac = (tid & 3) * 4;
    int br = tid >> 4, bc = (tid & 15) * 4;
    float acc[4][4];
#pragma unroll
    for (int i = 0; i < 4; i++)
#pragma unroll
        for (int j = 0; j < 4; j++) acc[i][j] = 0.f;

    for (int k0 = 0; k0 < K; k0 += 16) {
        float4 av = make_float4(0.f, 0.f, 0.f, 0.f);
        if (m0 + ar < M)
            av = *(const float4*)(A + (size_t)(m0 + ar) * K + k0 + ac);
        float4 bv = *(const float4*)(B + (size_t)(k0 + br) * Ncol + n0 + bc);
        __syncthreads();
        As[ac + 0][ar] = av.x; As[ac + 1][ar] = av.y;
        As[ac + 2][ar] = av.z; As[ac + 3][ar] = av.w;
        *(float4*)&Bs[br][bc] = bv;
        __syncthreads();
#pragma unroll
        for (int kk = 0; kk < 16; kk++) {
            float a0 = As[kk][ty * 4 + 0], a1 = As[kk][ty * 4 + 1];
            float a2 = As[kk][ty * 4 + 2], a3 = As[kk][ty * 4 + 3];
            float4 b = *(float4*)&Bs[kk][tx * 4];
            acc[0][0] += a0 * b.x; acc[0][1] += a0 * b.y; acc[0][2] += a0 * b.z; acc[0][3] += a0 * b.w;
            acc[1][0] += a1 * b.x; acc[1][1] += a1 * b.y; acc[1][2] += a1 * b.z; acc[1][3] += a1 * b.w;
            acc[2][0] += a2 * b.x; acc[2][1] += a2 * b.y; acc[2][2] += a2 * b.z; acc[2][3] += a2 * b.w;
            acc[3][0] += a3 * b.x; acc[3][1] += a3 * b.y; acc[3][2] += a3 * b.z; acc[3][3] += a3 * b.w;
        }
    }
#pragma unroll
    for (int i = 0; i < 4; i++) {
        int row = m0 + ty * 4 + i;
        if (row < M)
            *(float4*)(C + (size_t)row * Ncol + n0 + tx * 4) =
                make_float4(acc[i][0], acc[i][1], acc[i][2], acc[i][3]);
    }
}

__global__ void gemm1_kernel(const float* __restrict__ x, const float* __restrict__ W1) {
    gemm_body(x, W1, g_h1, NN, C1, FIN);
}
__global__ void gemm2_kernel(const float* __restrict__ W2) {
    gemm_body(g_out1, W2, g_h2, NN, HIDD, C1);
}

// ---------------- per-node attention logits, layer 1 (warp per node) ----------------
__global__ void logits1_kernel(const float* __restrict__ as1, const float* __restrict__ ad1) {
    int w = (blockIdx.x * blockDim.x + threadIdx.x) >> 5;
    int lane = threadIdx.x & 31;
    if (w >= NN) return;
    const float4* hp = (const float4*)(g_h1 + (size_t)w * C1);
    const float4* sp = (const float4*)as1;
    const float4* dp = (const float4*)ad1;
    float4 h0 = hp[lane * 2], h1v = hp[lane * 2 + 1];
    float4 s0 = sp[lane * 2], s1  = sp[lane * 2 + 1];
    float4 d0 = dp[lane * 2], d1  = dp[lane * 2 + 1];
    float ss = h0.x*s0.x + h0.y*s0.y + h0.z*s0.z + h0.w*s0.w
             + h1v.x*s1.x + h1v.y*s1.y + h1v.z*s1.z + h1v.w*s1.w;
    float dd = h0.x*d0.x + h0.y*d0.y + h0.z*d0.z + h0.w*d0.w
             + h1v.x*d1.x + h1v.y*d1.y + h1v.z*d1.z + h1v.w*d1.w;
    for (int o = 4; o; o >>= 1) {
        ss += __shfl_down_sync(0xffffffffu, ss, o, 8);
        dd += __shfl_down_sync(0xffffffffu, dd, o, 8);
    }
    if ((lane & 7) == 0) {
        g_als1[w * 4 + (lane >> 3)] = ss;
        g_ald1[w * 4 + (lane >> 3)] = dd;
    }
}

// ---------------- layer-1 exp(leakyrelu(logit)) per edge (no atomics) ----------------
__global__ void edgeA1_kernel(const int* __restrict__ ei, const float* __restrict__ ea) {
    int e = blockIdx.x * blockDim.x + threadIdx.x;
    if (e >= ELOOP) return;
    int s, d; float att;
    if (e < EE) { s = ei[e]; d = ei[EE + e]; att = ea[e]; }
    else        { s = d = e - EE; att = g_scal[0] * (1.0f / EE); }
    float4 as = *(const float4*)(g_als1 + s * 4);
    float4 ad = *(const float4*)(g_ald1 + d * 4);
    float z0 = as.x + ad.x + att * g_scal[1];
    float z1 = as.y + ad.y + att * g_scal[2];
    float z2 = as.z + ad.z + att * g_scal[3];
    float z3 = as.w + ad.w + att * g_scal[4];
    z0 = z0 > 0.f ? z0 : 0.2f * z0;
    z1 = z1 > 0.f ? z1 : 0.2f * z1;
    z2 = z2 > 0.f ? z2 : 0.2f * z2;
    z3 = z3 > 0.f ? z3 : 0.2f * z3;
    *(float4*)(g_ex1 + (size_t)e * 4) =
        make_float4(expf(z0), expf(z1), expf(z2), expf(z3));
}

// ---------------- layer-1 aggregation: warp per dst node, CSR, no atomics --------
__global__ void agg1_kernel(const float* __restrict__ b1) {
    int n = (blockIdx.x * blockDim.x + threadIdx.x) >> 5;
    int lane = threadIdx.x & 31;
    if (n >= NN) return;
    int beg = g_row[n], end = g_row[n + 1];
    int h = lane >> 3;                      // head of this lane
    float4 acc0 = make_float4(0.f, 0.f, 0.f, 0.f);
    float4 acc1 = make_float4(0.f, 0.f, 0.f, 0.f);
    float den = 0.f;
    for (int j = beg; j < end; j++) {
        int2 se = g_elist[j];
        float ex = g_ex1[(size_t)se.y * 4 + h];
        const float4* sp = (const float4*)(g_h1 + (size_t)se.x * C1);
        float4 v0 = sp[lane * 2], v1 = sp[lane * 2 + 1];
        den += ex;
        acc0.x += ex * v0.x; acc0.y += ex * v0.y; acc0.z += ex * v0.z; acc0.w += ex * v0.w;
        acc1.x += ex * v1.x; acc1.y += ex * v1.y; acc1.z += ex * v1.z; acc1.w += ex * v1.w;
    }
    float inv = 1.f / (den + 1e-16f);
    const float4* bp = (const float4*)b1;
    float4 bb0 = bp[lane * 2], bb1 = bp[lane * 2 + 1];
    float4 o0, o1;
    o0.x = fmaxf(acc0.x * inv + bb0.x, 0.f);
    o0.y = fmaxf(acc0.y * inv + bb0.y, 0.f);
    o0.z = fmaxf(acc0.z * inv + bb0.z, 0.f);
    o0.w = fmaxf(acc0.w * inv + bb0.w, 0.f);
    o1.x = fmaxf(acc1.x * inv + bb1.x, 0.f);
    o1.y = fmaxf(acc1.y * inv + bb1.y, 0.f);
    o1.z = fmaxf(acc1.z * inv + bb1.z, 0.f);
    o1.w = fmaxf(acc1.w * inv + bb1.w, 0.f);
    float4* op = (float4*)(g_out1 + (size_t)n * C1);
    op[lane * 2] = o0;
    op[lane * 2 + 1] = o1;
}

// ---------------- per-node logits, layer 2 (warp per node) ----------------
__global__ void logits2_kernel(const float* __restrict__ as2, const float* __restrict__ ad2) {
    int w = (blockIdx.x * blockDim.x + threadIdx.x) >> 5;
    int lane = threadIdx.x & 31;
    if (w >= NN) return;
    float2 v = ((const float2*)(g_h2 + (size_t)w * HIDD))[lane];
    float2 s = ((const float2*)as2)[lane];
    float2 dv = ((const float2*)ad2)[lane];
    float ss = v.x * s.x + v.y * s.y;
    float dd = v.x * dv.x + v.y * dv.y;
    for (int o = 16; o; o >>= 1) {
        ss += __shfl_xor_sync(0xffffffffu, ss, o);
        dd += __shfl_xor_sync(0xffffffffu, dd, o);
    }
    if (lane == 0) { g_als2[w] = ss; g_ald2[w] = dd; }
}

// ---------------- layer-2 exp(leakyrelu(logit)) per edge ----------------
__global__ void edgeA2_kernel(const int* __restrict__ ei, const float* __restrict__ ea) {
    int e = blockIdx.x * blockDim.x + threadIdx.x;
    if (e >= ELOOP) return;
    int s, d; float att;
    if (e < EE) { s = ei[e]; d = ei[EE + e]; att = ea[e]; }
    else        { s = d = e - EE; att = g_scal[0] * (1.0f / EE); }
    float z = g_als2[s] + g_ald2[d] + att * g_scal[5];
    z = z > 0.f ? z : 0.2f * z;
    g_ex2[e] = expf(z);
}

// ---------- layer-2 aggregation + bias + LayerNorm + pool (warp per node) --------
__global__ void agg2_ln_pool_kernel(const float* __restrict__ b2,
                                    const float* __restrict__ lng,
                                    const float* __restrict__ lnb,
                                    const int* __restrict__ batch) {
    int n = (blockIdx.x * blockDim.x + threadIdx.x) >> 5;
    int lane = threadIdx.x & 31;
    if (n >= NN) return;
    int beg = g_row[n], end = g_row[n + 1];
    float2 acc = make_float2(0.f, 0.f);
    float den = 0.f;
    for (int j = beg; j < end; j++) {
        int2 se = g_elist[j];
        float ex = g_ex2[se.y];
        float2 v = ((const float2*)(g_h2 + (size_t)se.x * HIDD))[lane];
        den += ex;
        acc.x += ex * v.x;
        acc.y += ex * v.y;
    }
    float inv = 1.f / (den + 1e-16f);
    float2 bb = ((const float2*)b2)[lane];
    float vx = acc.x * inv + bb.x;
    float vy = acc.y * inv + bb.y;
    // LayerNorm over the 64 values held by this warp
    float s = vx + vy;
    for (int o = 16; o; o >>= 1) s += __shfl_xor_sync(0xffffffffu, s, o);
    float mu = s * (1.0f / 64.0f);
    float dx = vx - mu, dy = vy - mu;
    float q = dx * dx + dy * dy;
    for (int o = 16; o; o >>= 1) q += __shfl_xor_sync(0xffffffffu, q, o);
    float r = rsqrtf(q * (1.0f / 64.0f) + 1e-5f);
    float y0 = dx * r * lng[lane * 2]     + lnb[lane * 2];
    float y1 = dy * r * lng[lane * 2 + 1] + lnb[lane * 2 + 1];
    int g = batch[n];
    atomicAdd(&g_sums[g * 64 + lane * 2],     y0);
    atomicAdd(&g_sums[g * 64 + lane * 2 + 1], y1);
    if (lane == 0) atomicAdd(&g_cnt[g], 1.0f);
}

// ---------------- per-graph MLP head (block per graph, 64 threads) ----------------
__global__ void mlp_kernel(const float* __restrict__ clin, const float* __restrict__ met,
                           const float* __restrict__ Wf1, const float* __restrict__ bf1,
                           const float* __restrict__ Wf2, const float* __restrict__ bf2,
                           const float* __restrict__ Wr,  const float* __restrict__ br,
                           float* __restrict__ out) {
    int g = blockIdx.x, t = threadIdx.x;   // 64 threads
    __shared__ float fused[FUSED_IN];
    __shared__ float l1[64];
    __shared__ float l2[32];
    float cnt = g_cnt[g]; cnt = cnt > 1.f ? cnt : 1.f;
    float e = g_sums[g * 64 + t] / cnt;
    fused[t] = e;
    out[GG + g * 64 + t] = e;              // graph_embedding at offset 64
    if (t < 32) fused[64 + t] = clin[g * 32 + t];
    fused[96 + t]  = met[g * 128 + t];
    fused[160 + t] = met[g * 128 + 64 + t];
    __syncthreads();
    float acc = bf1[t];
#pragma unroll 8
    for (int k = 0; k < FUSED_IN; k++) acc += fused[k] * Wf1[k * 64 + t];
    l1[t] = acc > 0.f ? acc : 0.f;
    __syncthreads();
    if (t < 32) {
        float a2 = bf2[t];
#pragma unroll 8
        for (int j = 0; j < 64; j++) a2 += l1[j] * Wf2[j * 32 + t];
        a2 = a2 > 0.f ? a2 : 0.f;
        l2[t] = a2;
        out[GG + GG * 64 + g * 32 + t] = a2;   // latent at offset 64 + 4096
    }
    __syncthreads();
    if (t == 0) {
        float r = br[0];
#pragma unroll
        for (int j = 0; j < 32; j++) r += l2[j] * Wr[j];
        out[g] = r;                        // risk at offset 0
    }
}

// ---------------- launch ----------------
extern "C" void kernel_launch(void* const* d_in, const int* in_sizes, int n_in,
                              void* d_out, int out_size) {
    const float* x    = (const float*)d_in[0];
    const int*   ei   = (const int*)d_in[1];
    const float* ea   = (const float*)d_in[2];
    const int*   bat  = (const int*)d_in[3];
    const float* clin = (const float*)d_in[4];
    const float* met  = (const float*)d_in[5];
    const float* W1   = (const float*)d_in[6];
    const float* as1  = (const float*)d_in[7];
    const float* ad1  = (const float*)d_in[8];
    const float* ae1  = (const float*)d_in[9];
    const float* We1  = (const float*)d_in[10];
    const float* b1   = (const float*)d_in[11];
    const float* W2   = (const float*)d_in[12];
    const float* as2  = (const float*)d_in[13];
    const float* ad2  = (const float*)d_in[14];
    const float* ae2  = (const float*)d_in[15];
    const float* We2  = (const float*)d_in[16];
    const float* b2   = (const float*)d_in[17];
    const float* lng  = (const float*)d_in[18];
    const float* lnb  = (const float*)d_in[19];
    const float* Wf1  = (const float*)d_in[20];
    const float* bf1  = (const float*)d_in[21];
    const float* Wf2  = (const float*)d_in[22];
    const float* bf2  = (const float*)d_in[23];
    const float* Wr   = (const float*)d_in[24];
    const float* br   = (const float*)d_in[25];
    float* out = (float*)d_out;

    zero_small_kernel<<<(NN + 255) / 256, 256>>>();
    mean_ea_kernel<<<512, 256>>>(ea);
    ce_kernel<<<1, 256>>>(We1, ae1, We2, ae2);

    // CSR build (by dst)
    hist_kernel<<<(ELOOP + 255) / 256, 256>>>(ei);
    scan_kernel<<<1, 1024>>>();
    scatter_kernel<<<(ELOOP + 255) / 256, 256>>>(ei);

    // layer 1
    gemm1_kernel<<<dim3(C1 / 64, (NN + 63) / 64), 256>>>(x, W1);
    logits1_kernel<<<(NN * 32 + 255) / 256, 256>>>(as1, ad1);
    edgeA1_kernel<<<(ELOOP + 255) / 256, 256>>>(ei, ea);
    agg1_kernel<<<(NN * 32 + 255) / 256, 256>>>(b1);

    // layer 2
    gemm2_kernel<<<dim3(HIDD / 64, (NN + 63) / 64), 256>>>(W2);
    logits2_kernel<<<(NN * 32 + 255) / 256, 256>>>(as2, ad2);
    edgeA2_kernel<<<(ELOOP + 255) / 256, 256>>>(ei, ea);
    agg2_ln_pool_kernel<<<(NN * 32 + 255) / 256, 256>>>(b2, lng, lnb, bat);

    // head
    mlp_kernel<<<GG, 64>>>(clin, met, Wf1, bf1, Wf2, bf2, Wr, br, out);
}

// round 5
// speedup vs baseline: 3.2850x; 1.0776x over previous
#include <cuda_runtime.h>

// ---------------- fixed problem shapes ----------------
#define NN      50000
#define EE      800000
#define ELOOP   850000        // EE + NN self loops
#define GG      64
#define FIN     128
#define HIDD    64
#define HEADS   4
#define C1      256           // HEADS*HIDD
#define CLIN    32
#define MET     128
#define FUSED_IN 224          // HIDD + CLIN + MET

// ---------------- device scratch (no allocs allowed) ----------------
__device__ float g_h1  [(size_t)NN * C1];     // x @ W1
__device__ float g_out1[(size_t)NN * C1];     // layer1 output (post bias+relu)
__device__ float g_h2  [(size_t)NN * HIDD];   // out1 @ W2
__device__ float g_als1[NN * HEADS];
__device__ float g_ald1[NN * HEADS];
__device__ float g_als2[NN];
__device__ float g_ald2[NN];
__device__ float g_sums[GG * HIDD];
__device__ float g_cnt [GG];
__device__ float g_scal[8];     // [0]=sum(edge_attr), [1..4]=ce1[h], [5]=ce2
// CSR by destination
__device__ int  g_row [NN + 1];
__device__ int  g_cur [NN];     // hist -> cursor
__device__ int2 g_elist[ELOOP]; // (src, float_bits(edge_attr)) sorted by dst

// ---------------- zero the small scratch ----------------
__global__ void zero_small_kernel() {
    int i = blockIdx.x * blockDim.x + threadIdx.x;
    if (i < NN) g_cur[i] = 0;
    if (i < GG * HIDD) g_sums[i] = 0.f;
    if (i < GG) g_cnt[i] = 0.f;
    if (i < 8)  g_scal[i] = 0.f;
}

// ---------------- mean(edge_attr): SUM into g_scal[0] ----------------
__global__ void mean_ea_kernel(const float* __restrict__ ea) {
    __shared__ float sh[8];
    size_t stride = (size_t)gridDim.x * blockDim.x;
    float s = 0.f;
    for (size_t i = (size_t)blockIdx.x * blockDim.x + threadIdx.x; i < EE; i += stride)
        s += ea[i];
    for (int o = 16; o; o >>= 1) s += __shfl_xor_sync(0xffffffffu, s, o);
    if ((threadIdx.x & 31) == 0) sh[threadIdx.x >> 5] = s;
    __syncthreads();
    if (threadIdx.x < 8) {
        float v = sh[threadIdx.x];
        for (int o = 4; o; o >>= 1) v += __shfl_xor_sync(0xffu, v, o);
        if (threadIdx.x == 0) atomicAdd(&g_scal[0], v);
    }
}

// ---------------- ce1[h] = We1.ae1 per head ; ce2 = We2.ae2 ----------------
__global__ void ce_kernel(const float* __restrict__ We1, const float* __restrict__ ae1,
                          const float* __restrict__ We2, const float* __restrict__ ae2) {
    int t = threadIdx.x;                       // 256 threads
    atomicAdd(&g_scal[1 + (t >> 6)], We1[t] * ae1[t]);
    if (t < 64) atomicAdd(&g_scal[5], We2[t] * ae2[t]);
}

// ---------------- CSR build: histogram of dst ----------------
__global__ void hist_kernel(const int* __restrict__ ei) {
    int e = blockIdx.x * blockDim.x + threadIdx.x;
    if (e >= ELOOP) return;
    int d = (e < EE) ? ei[EE + e] : (e - EE);
    atomicAdd(&g_cur[d], 1);
}

// ---------------- CSR build: exclusive scan (single block, 1024 thr) ----------------
#define CHUNK 49   // 1024*49 = 50176 >= NN
__global__ void scan_kernel() {
    __shared__ int ps[1024];
    int t = threadIdx.x;
    int base = t * CHUNK;
    int s = 0;
    for (int i = 0; i < CHUNK; i++) {
        int idx = base + i;
        if (idx < NN) s += g_cur[idx];
    }
    ps[t] = s;
    __syncthreads();
    for (int off = 1; off < 1024; off <<= 1) {
        int v = (t >= off) ? ps[t - off] : 0;
        __syncthreads();
        ps[t] += v;
        __syncthreads();
    }
    int run = ps[t] - s;
    for (int i = 0; i < CHUNK; i++) {
        int idx = base + i;
        if (idx < NN) {
            int d = g_cur[idx];
            g_row[idx] = run;
            g_cur[idx] = run;
            run += d;
        }
    }
    if (t == 0) g_row[NN] = ELOOP;
}

// ---------------- CSR build: scatter (src, edge_attr) ----------------
__global__ void scatter_kernel(const int* __restrict__ ei, const float* __restrict__ ea) {
    int e = blockIdx.x * blockDim.x + threadIdx.x;
    if (e >= ELOOP) return;
    int s, d; float att;
    if (e < EE) { s = ei[e]; d = ei[EE + e]; att = ea[e]; }
    else        { s = d = e - EE; att = g_scal[0] * (1.0f / EE); }
    int pos = atomicAdd(&g_cur[d], 1);
    g_elist[pos] = make_int2(s, __float_as_int(att));
}

// ---------------- tiled SGEMM body: BM=128, BK=8, 256 threads ----------------
// BN in {128, 64}; TM=8, TN = BN/16. Called ONLY from device wrappers so that
// g_* device symbols are referenced from device code.
template<int BN, int TN>
__device__ __forceinline__ void gemm_body(const float* __restrict__ A,
                                          const float* __restrict__ B,
                                          float* __restrict__ C,
                                          int M, int Ncol, int K) {
    __shared__ float As[8][132];
    __shared__ float Bs[8][BN];
    int tid = threadIdx.x;
    int tx = tid & 15, ty = tid >> 4;
    int m0 = blockIdx.y * 128, n0 = blockIdx.x * BN;

    int lam = tid >> 1, lak = (tid & 1) * 4;   // A loader
    int lbr, lbc;                               // B loader
    if (BN == 128) { lbr = tid >> 5; lbc = (tid & 31) * 4; }
    else           { lbr = tid >> 4; lbc = (tid & 15) * 4; }

    float acc[8][TN];
#pragma unroll
    for (int i = 0; i < 8; i++)
#pragma unroll
        for (int j = 0; j < TN; j++) acc[i][j] = 0.f;

    for (int k0 = 0; k0 < K; k0 += 8) {
        float4 av = make_float4(0.f, 0.f, 0.f, 0.f);
        if (m0 + lam < M)
            av = *(const float4*)(A + (size_t)(m0 + lam) * K + k0 + lak);
        float4 bv = make_float4(0.f, 0.f, 0.f, 0.f);
        bool bld = (BN == 128) || (tid < 128);
        if (bld)
            bv = *(const float4*)(B + (size_t)(k0 + lbr) * Ncol + n0 + lbc);
        __syncthreads();
        As[lak + 0][lam] = av.x;
        As[lak + 1][lam] = av.y;
        As[lak + 2][lam] = av.z;
        As[lak + 3][lam] = av.w;
        if (bld) *(float4*)&Bs[lbr][lbc] = bv;
        __syncthreads();
#pragma unroll
        for (int kk = 0; kk < 8; kk++) {
            float4 a0 = *(float4*)&As[kk][ty * 8];
            float4 a1 = *(float4*)&As[kk][ty * 8 + 4];
            float af[8] = {a0.x, a0.y, a0.z, a0.w, a1.x, a1.y, a1.z, a1.w};
            float bf[TN];
            if (TN == 8) {
                float4 b0 = *(float4*)&Bs[kk][tx * 8];
                float4 b1 = *(float4*)&Bs[kk][tx * 8 + 4];
                bf[0] = b0.x; bf[1] = b0.y; bf[2] = b0.z; bf[3] = b0.w;
                bf[4] = b1.x; bf[5] = b1.y; bf[6] = b1.z; bf[7] = b1.w;
            } else {
                float4 b0 = *(float4*)&Bs[kk][tx * 4];
                bf[0] = b0.x; bf[1] = b0.y; bf[2] = b0.z; bf[3] = b0.w;
            }
#pragma unroll
            for (int i = 0; i < 8; i++)
#pragma unroll
                for (int j = 0; j < TN; j++)
                    acc[i][j] += af[i] * bf[j];
        }
    }
#pragma unroll
    for (int i = 0; i < 8; i++) {
        int row = m0 + ty * 8 + i;
        if (row < M) {
            float* cp = C + (size_t)row * Ncol + n0 + tx * TN;
#pragma unroll
            for (int j = 0; j < TN; j += 4)
                *(float4*)(cp + j) = make_float4(acc[i][j], acc[i][j+1], acc[i][j+2], acc[i][j+3]);
        }
    }
}

// wrappers: device-side references to g_* symbols
__global__ void gemm1_kernel(const float* __restrict__ x, const float* __restrict__ W1) {
    gemm_body<128, 8>(x, W1, g_h1, NN, C1, FIN);
}
__global__ void gemm2_kernel(const float* __restrict__ W2) {
    gemm_body<64, 4>(g_out1, W2, g_h2, NN, HIDD, C1);
}

// ---------------- per-node attention logits, layer 1 (warp per node) ----------------
__global__ void logits1_kernel(const float* __restrict__ as1, const float* __restrict__ ad1) {
    int w = (blockIdx.x * blockDim.x + threadIdx.x) >> 5;
    int lane = threadIdx.x & 31;
    if (w >= NN) return;
    const float4* hp = (const float4*)(g_h1 + (size_t)w * C1);
    const float4* sp = (const float4*)as1;
    const float4* dp = (const float4*)ad1;
    float4 h0 = hp[lane * 2], h1v = hp[lane * 2 + 1];
    float4 s0 = sp[lane * 2], s1  = sp[lane * 2 + 1];
    float4 d0 = dp[lane * 2], d1  = dp[lane * 2 + 1];
    float ss = h0.x*s0.x + h0.y*s0.y + h0.z*s0.z + h0.w*s0.w
             + h1v.x*s1.x + h1v.y*s1.y + h1v.z*s1.z + h1v.w*s1.w;
    float dd = h0.x*d0.x + h0.y*d0.y + h0.z*d0.z + h0.w*d0.w
             + h1v.x*d1.x + h1v.y*d1.y + h1v.z*d1.z + h1v.w*d1.w;
    for (int o = 4; o; o >>= 1) {
        ss += __shfl_down_sync(0xffffffffu, ss, o, 8);
        dd += __shfl_down_sync(0xffffffffu, dd, o, 8);
    }
    if ((lane & 7) == 0) {
        g_als1[w * 4 + (lane >> 3)] = ss;
        g_ald1[w * 4 + (lane >> 3)] = dd;
    }
}

// ---- layer-1 aggregation (fused attention softmax): warp per dst node ----
__global__ void agg1_kernel(const float* __restrict__ b1) {
    int n = (blockIdx.x * blockDim.x + threadIdx.x) >> 5;
    int lane = threadIdx.x & 31;
    if (n >= NN) return;
    int beg = g_row[n], end = g_row[n + 1];
    int h = lane >> 3;
    float ald = g_ald1[n * 4 + h];
    float ce  = g_scal[1 + h];
    float4 acc0 = make_float4(0.f, 0.f, 0.f, 0.f);
    float4 acc1 = make_float4(0.f, 0.f, 0.f, 0.f);
    float den = 0.f;
    int j = beg;
    for (; j + 2 <= end; j += 2) {
        int2 se0 = g_elist[j];
        int2 se1 = g_elist[j + 1];
        float als0 = g_als1[se0.x * 4 + h];
        float als1v = g_als1[se1.x * 4 + h];
        const float4* sp0 = (const float4*)(g_h1 + (size_t)se0.x * C1);
        const float4* sp1 = (const float4*)(g_h1 + (size_t)se1.x * C1);
        float4 u0 = sp0[lane * 2], u1 = sp0[lane * 2 + 1];
        float4 v0 = sp1[lane * 2], v1 = sp1[lane * 2 + 1];
        float z0 = als0 + ald + __int_as_float(se0.y) * ce;
        float z1 = als1v + ald + __int_as_float(se1.y) * ce;
        z0 = z0 > 0.f ? z0 : 0.2f * z0;
        z1 = z1 > 0.f ? z1 : 0.2f * z1;
        float ex0 = expf(z0), ex1 = expf(z1);
        den += ex0 + ex1;
        acc0.x += ex0 * u0.x + ex1 * v0.x;
        acc0.y += ex0 * u0.y + ex1 * v0.y;
        acc0.z += ex0 * u0.z + ex1 * v0.z;
        acc0.w += ex0 * u0.w + ex1 * v0.w;
        acc1.x += ex0 * u1.x + ex1 * v1.x;
        acc1.y += ex0 * u1.y + ex1 * v1.y;
        acc1.z += ex0 * u1.z + ex1 * v1.z;
        acc1.w += ex0 * u1.w + ex1 * v1.w;
    }
    if (j < end) {
        int2 se = g_elist[j];
        float als = g_als1[se.x * 4 + h];
        const float4* sp = (const float4*)(g_h1 + (size_t)se.x * C1);
        float4 u0 = sp[lane * 2], u1 = sp[lane * 2 + 1];
        float z = als + ald + __int_as_float(se.y) * ce;
        z = z > 0.f ? z : 0.2f * z;
        float ex = expf(z);
        den += ex;
        acc0.x += ex * u0.x; acc0.y += ex * u0.y; acc0.z += ex * u0.z; acc0.w += ex * u0.w;
        acc1.x += ex * u1.x; acc1.y += ex * u1.y; acc1.z += ex * u1.z; acc1.w += ex * u1.w;
    }
    float inv = 1.f / (den + 1e-16f);
    const float4* bp = (const float4*)b1;
    float4 bb0 = bp[lane * 2], bb1 = bp[lane * 2 + 1];
    float4 o0, o1;
    o0.x = fmaxf(acc0.x * inv + bb0.x, 0.f);
    o0.y = fmaxf(acc0.y * inv + bb0.y, 0.f);
    o0.z = fmaxf(acc0.z * inv + bb0.z, 0.f);
    o0.w = fmaxf(acc0.w * inv + bb0.w, 0.f);
    o1.x = fmaxf(acc1.x * inv + bb1.x, 0.f);
    o1.y = fmaxf(acc1.y * inv + bb1.y, 0.f);
    o1.z = fmaxf(acc1.z * inv + bb1.z, 0.f);
    o1.w = fmaxf(acc1.w * inv + bb1.w, 0.f);
    float4* op = (float4*)(g_out1 + (size_t)n * C1);
    op[lane * 2] = o0;
    op[lane * 2 + 1] = o1;
}

// ---------------- per-node logits, layer 2 (warp per node) ----------------
__global__ void logits2_kernel(const float* __restrict__ as2, const float* __restrict__ ad2) {
    int w = (blockIdx.x * blockDim.x + threadIdx.x) >> 5;
    int lane = threadIdx.x & 31;
    if (w >= NN) return;
    float2 v = ((const float2*)(g_h2 + (size_t)w * HIDD))[lane];
    float2 s = ((const float2*)as2)[lane];
    float2 dv = ((const float2*)ad2)[lane];
    float ss = v.x * s.x + v.y * s.y;
    float dd = v.x * dv.x + v.y * dv.y;
    for (int o = 16; o; o >>= 1) {
        ss += __shfl_xor_sync(0xffffffffu, ss, o);
        dd += __shfl_xor_sync(0xffffffffu, dd, o);
    }
    if (lane == 0) { g_als2[w] = ss; g_ald2[w] = dd; }
}

// ---- layer-2 aggregation (fused attention) + bias + LayerNorm + pool ----
__global__ void agg2_ln_pool_kernel(const float* __restrict__ b2,
                                    const float* __restrict__ lng,
                                    const float* __restrict__ lnb,
                                    const int* __restrict__ batch) {
    int n = (blockIdx.x * blockDim.x + threadIdx.x) >> 5;
    int lane = threadIdx.x & 31;
    if (n >= NN) return;
    int beg = g_row[n], end = g_row[n + 1];
    float ald = g_ald2[n];
    float ce  = g_scal[5];
    float2 acc = make_float2(0.f, 0.f);
    float den = 0.f;
    int j = beg;
    for (; j + 2 <= end; j += 2) {
        int2 se0 = g_elist[j];
        int2 se1 = g_elist[j + 1];
        float als0 = g_als2[se0.x];
        float als1v = g_als2[se1.x];
        float2 u = ((const float2*)(g_h2 + (size_t)se0.x * HIDD))[lane];
        float2 v = ((const float2*)(g_h2 + (size_t)se1.x * HIDD))[lane];
        float z0 = als0 + ald + __int_as_float(se0.y) * ce;
        float z1 = als1v + ald + __int_as_float(se1.y) * ce;
        z0 = z0 > 0.f ? z0 : 0.2f * z0;
        z1 = z1 > 0.f ? z1 : 0.2f * z1;
        float ex0 = expf(z0), ex1 = expf(z1);
        den += ex0 + ex1;
        acc.x += ex0 * u.x + ex1 * v.x;
        acc.y += ex0 * u.y + ex1 * v.y;
    }
    if (j < end) {
        int2 se = g_elist[j];
        float als = g_als2[se.x];
        float2 u = ((const float2*)(g_h2 + (size_t)se.x * HIDD))[lane];
        float z = als + ald + __int_as_float(se.y) * ce;
        z = z > 0.f ? z : 0.2f * z;
        float ex = expf(z);
        den += ex;
        acc.x += ex * u.x;
        acc.y += ex * u.y;
    }
    float inv = 1.f / (den + 1e-16f);
    float2 bb = ((const float2*)b2)[lane];
    float vx = acc.x * inv + bb.x;
    float vy = acc.y * inv + bb.y;
    float s = vx + vy;
    for (int o = 16; o; o >>= 1) s += __shfl_xor_sync(0xffffffffu, s, o);
    float mu = s * (1.0f / 64.0f);
    float dx = vx - mu, dy = vy - mu;
    float q = dx * dx + dy * dy;
    for (int o = 16; o; o >>= 1) q += __shfl_xor_sync(0xffffffffu, q, o);
    float r = rsqrtf(q * (1.0f / 64.0f) + 1e-5f);
    float y0 = dx * r * lng[lane * 2]     + lnb[lane * 2];
    float y1 = dy * r * lng[lane * 2 + 1] + lnb[lane * 2 + 1];
    int g = batch[n];
    atomicAdd(&g_sums[g * 64 + lane * 2],     y0);
    atomicAdd(&g_sums[g * 64 + lane * 2 + 1], y1);
    if (lane == 0) atomicAdd(&g_cnt[g], 1.0f);
}

// ---------------- per-graph MLP head (block per graph, 64 threads) ----------------
__global__ void mlp_kernel(const float* __restrict__ clin, const float* __restrict__ met,
                           const float* __restrict__ Wf1, const float* __restrict__ bf1,
                           const float* __restrict__ Wf2, const float* __restrict__ bf2,
                           const float* __restrict__ Wr,  const float* __restrict__ br,
                           float* __restrict__ out) {
    int g = blockIdx.x, t = threadIdx.x;   // 64 threads
    __shared__ float fused[FUSED_IN];
    __shared__ float l1[64];
    __shared__ float l2[32];
    float cnt = g_cnt[g]; cnt = cnt > 1.f ? cnt : 1.f;
    float e = g_sums[g * 64 + t] / cnt;
    fused[t] = e;
    out[GG + g * 64 + t] = e;              // graph_embedding at offset 64
    if (t < 32) fused[64 + t] = clin[g * 32 + t];
    fused[96 + t]  = met[g * 128 + t];
    fused[160 + t] = met[g * 128 + 64 + t];
    __syncthreads();
    float acc = bf1[t];
#pragma unroll 8
    for (int k = 0; k < FUSED_IN; k++) acc += fused[k] * Wf1[k * 64 + t];
    l1[t] = acc > 0.f ? acc : 0.f;
    __syncthreads();
    if (t < 32) {
        float a2 = bf2[t];
#pragma unroll 8
        for (int j = 0; j < 64; j++) a2 += l1[j] * Wf2[j * 32 + t];
        a2 = a2 > 0.f ? a2 : 0.f;
        l2[t] = a2;
        out[GG + GG * 64 + g * 32 + t] = a2;   // latent at offset 64 + 4096
    }
    __syncthreads();
    if (t == 0) {
        float r = br[0];
#pragma unroll
        for (int j = 0; j < 32; j++) r += l2[j] * Wr[j];
        out[g] = r;                        // risk at offset 0
    }
}

// ---------------- launch ----------------
extern "C" void kernel_launch(void* const* d_in, const int* in_sizes, int n_in,
                              void* d_out, int out_size) {
    const float* x    = (const float*)d_in[0];
    const int*   ei   = (const int*)d_in[1];
    const float* ea   = (const float*)d_in[2];
    const int*   bat  = (const int*)d_in[3];
    const float* clin = (const float*)d_in[4];
    const float* met  = (const float*)d_in[5];
    const float* W1   = (const float*)d_in[6];
    const float* as1  = (const float*)d_in[7];
    const float* ad1  = (const float*)d_in[8];
    const float* ae1  = (const float*)d_in[9];
    const float* We1  = (const float*)d_in[10];
    const float* b1   = (const float*)d_in[11];
    const float* W2   = (const float*)d_in[12];
    const float* as2  = (const float*)d_in[13];
    const float* ad2  = (const float*)d_in[14];
    const float* ae2  = (const float*)d_in[15];
    const float* We2  = (const float*)d_in[16];
    const float* b2   = (const float*)d_in[17];
    const float* lng  = (const float*)d_in[18];
    const float* lnb  = (const float*)d_in[19];
    const float* Wf1  = (const float*)d_in[20];
    const float* bf1  = (const float*)d_in[21];
    const float* Wf2  = (const float*)d_in[22];
    const float* bf2  = (const float*)d_in[23];
    const float* Wr   = (const float*)d_in[24];
    const float* br   = (const float*)d_in[25];
    float* out = (float*)d_out;

    zero_small_kernel<<<(NN + 255) / 256, 256>>>();
    mean_ea_kernel<<<512, 256>>>(ea);
    ce_kernel<<<1, 256>>>(We1, ae1, We2, ae2);

    // CSR build (by dst), with edge_attr fused into the list
    hist_kernel<<<(ELOOP + 255) / 256, 256>>>(ei);
    scan_kernel<<<1, 1024>>>();
    scatter_kernel<<<(ELOOP + 255) / 256, 256>>>(ei, ea);

    // layer 1
    gemm1_kernel<<<dim3(C1 / 128, (NN + 127) / 128), 256>>>(x, W1);
    logits1_kernel<<<(NN * 32 + 255) / 256, 256>>>(as1, ad1);
    agg1_kernel<<<(NN * 32 + 255) / 256, 256>>>(b1);

    // layer 2
    gemm2_kernel<<<dim3(HIDD / 64, (NN + 127) / 128), 256>>>(W2);
    logits2_kernel<<<(NN * 32 + 255) / 256, 256>>>(as2, ad2);
    agg2_ln_pool_kernel<<<(NN * 32 + 255) / 256, 256>>>(b2, lng, lnb, bat);

    // head
    mlp_kernel<<<GG, 64>>>(clin, met, Wf1, bf1, Wf2, bf2, Wr, br, out);
}

// round 6
// speedup vs baseline: 3.7711x; 1.1480x over previous
#include <cuda_runtime.h>
#include <cstdint>

// ---------------- fixed problem shapes ----------------
#define NN      50000
#define EE      800000
#define ELOOP   850000        // EE + NN self loops
#define GG      64
#define FIN     128
#define HIDD    64
#define HEADS   4
#define C1      256           // HEADS*HIDD
#define CLIN    32
#define MET     128
#define FUSED_IN 224          // HIDD + CLIN + MET

// ---------------- device scratch (no allocs allowed) ----------------
__device__ float g_h1  [(size_t)NN * C1];     // x @ W1
__device__ float g_out1[(size_t)NN * C1];     // layer1 output (post bias+relu)
__device__ float g_h2  [(size_t)NN * HIDD];   // out1 @ W2
__device__ float g_als1[NN * HEADS];
__device__ float g_ald1[NN * HEADS];
__device__ float g_als2[NN];
__device__ float g_ald2[NN];
__device__ float g_sums[GG * HIDD];
__device__ float g_cnt [GG];
__device__ float g_scal[8];     // [0]=sum(edge_attr), [1..4]=ce1[h], [5]=ce2
// CSR by destination
__device__ int  g_row [NN + 1];
__device__ int  g_cur [NN];     // hist -> cursor
__device__ int2 g_elist[ELOOP]; // (src, float_bits(edge_attr)) sorted by dst

// ---------------- zero the small scratch ----------------
__global__ void zero_small_kernel() {
    int i = blockIdx.x * blockDim.x + threadIdx.x;
    if (i < NN) g_cur[i] = 0;
    if (i < GG * HIDD) g_sums[i] = 0.f;
    if (i < GG) g_cnt[i] = 0.f;
    if (i < 8)  g_scal[i] = 0.f;
}

// ---------------- mean(edge_attr): SUM into g_scal[0] ----------------
__global__ void mean_ea_kernel(const float* __restrict__ ea) {
    __shared__ float sh[8];
    size_t stride = (size_t)gridDim.x * blockDim.x;
    float s = 0.f;
    for (size_t i = (size_t)blockIdx.x * blockDim.x + threadIdx.x; i < EE; i += stride)
        s += ea[i];
    for (int o = 16; o; o >>= 1) s += __shfl_xor_sync(0xffffffffu, s, o);
    if ((threadIdx.x & 31) == 0) sh[threadIdx.x >> 5] = s;
    __syncthreads();
    if (threadIdx.x < 8) {
        float v = sh[threadIdx.x];
        for (int o = 4; o; o >>= 1) v += __shfl_xor_sync(0xffu, v, o);
        if (threadIdx.x == 0) atomicAdd(&g_scal[0], v);
    }
}

// ---------------- ce1[h] = We1.ae1 per head ; ce2 = We2.ae2 ----------------
__global__ void ce_kernel(const float* __restrict__ We1, const float* __restrict__ ae1,
                          const float* __restrict__ We2, const float* __restrict__ ae2) {
    int t = threadIdx.x;                       // 256 threads
    atomicAdd(&g_scal[1 + (t >> 6)], We1[t] * ae1[t]);
    if (t < 64) atomicAdd(&g_scal[5], We2[t] * ae2[t]);
}

// ---------------- CSR build: histogram of dst ----------------
__global__ void hist_kernel(const int* __restrict__ ei) {
    int e = blockIdx.x * blockDim.x + threadIdx.x;
    if (e >= ELOOP) return;
    int d = (e < EE) ? ei[EE + e] : (e - EE);
    atomicAdd(&g_cur[d], 1);
}

// ---------------- CSR build: exclusive scan (single block, 1024 thr) ----------------
#define CHUNK 49   // 1024*49 = 50176 >= NN
__global__ void scan_kernel() {
    __shared__ int ps[1024];
    int t = threadIdx.x;
    int base = t * CHUNK;
    int s = 0;
    for (int i = 0; i < CHUNK; i++) {
        int idx = base + i;
        if (idx < NN) s += g_cur[idx];
    }
    ps[t] = s;
    __syncthreads();
    for (int off = 1; off < 1024; off <<= 1) {
        int v = (t >= off) ? ps[t - off] : 0;
        __syncthreads();
        ps[t] += v;
        __syncthreads();
    }
    int run = ps[t] - s;
    for (int i = 0; i < CHUNK; i++) {
        int idx = base + i;
        if (idx < NN) {
            int d = g_cur[idx];
            g_row[idx] = run;
            g_cur[idx] = run;
            run += d;
        }
    }
    if (t == 0) g_row[NN] = ELOOP;
}

// ---------------- CSR build: scatter (src, edge_attr) ----------------
__global__ void scatter_kernel(const int* __restrict__ ei, const float* __restrict__ ea) {
    int e = blockIdx.x * blockDim.x + threadIdx.x;
    if (e >= ELOOP) return;
    int s, d; float att;
    if (e < EE) { s = ei[e]; d = ei[EE + e]; att = ea[e]; }
    else        { s = d = e - EE; att = g_scal[0] * (1.0f / EE); }
    int pos = atomicAdd(&g_cur[d], 1);
    g_elist[pos] = make_int2(s, __float_as_int(att));
}

// ---------------- TF32 tensor-core GEMM ----------------
__device__ __forceinline__ uint32_t f2tf32(float f) {
    uint32_t r;
    asm("cvt.rna.tf32.f32 %0, %1;" : "=r"(r) : "f"(f));
    return r;
}

// C[M,Ncol] = A[M,K] @ B[K,Ncol], row-major. BM=128, BK=16, 256 threads (8 warps, 4x2).
// Warp tile: 32 x (BN/2). mma.sync m16n8k8 tf32, fp32 accumulate.
template<int BN, int K>
__device__ __forceinline__ void gemm_tf32_body(const float* __restrict__ A,
                                               const float* __restrict__ B,
                                               float* __restrict__ C,
                                               int M, int Ncol) {
    constexpr int NF = BN / 2 / 8;           // n-fragments per warp (8 or 4)
    __shared__ uint32_t As[128][20];         // 128 x 16, stride 20 (conflict-free)
    __shared__ uint32_t Bs[16][BN + 4];      // 16 x BN, stride BN+4
    int tid = threadIdx.x;
    int warp = tid >> 5, lane = tid & 31;
    int warp_m = warp & 3;                   // 0..3 : 32 rows each
    int warp_n = warp >> 2;                  // 0..1 : BN/2 cols each
    int m0 = blockIdx.y * 128, n0 = blockIdx.x * BN;
    int g = lane >> 2, t4 = lane & 3;        // mma groupID / threadID-in-group

    float acc[2][NF][4];
#pragma unroll
    for (int mf = 0; mf < 2; mf++)
#pragma unroll
        for (int nf = 0; nf < NF; nf++)
#pragma unroll
            for (int i = 0; i < 4; i++) acc[mf][nf][i] = 0.f;

    for (int k0 = 0; k0 < K; k0 += 16) {
        // load A tile: 128x16 = 512 float4, 2 per thread
#pragma unroll
        for (int i = 0; i < 2; i++) {
            int fid = tid * 2 + i;
            int r = fid >> 2, c4 = (fid & 3) * 4;
            float4 av = make_float4(0.f, 0.f, 0.f, 0.f);
            if (m0 + r < M)
                av = *(const float4*)(A + (size_t)(m0 + r) * K + k0 + c4);
            uint4 tv = make_uint4(f2tf32(av.x), f2tf32(av.y), f2tf32(av.z), f2tf32(av.w));
            if (k0 == 0) { /* first iter smem not yet read */ }
            __syncthreads();   // protect smem reuse across k iterations
            *(uint4*)&As[r][c4] = tv;
            // B tile: 16 x BN floats
            if (BN == 128) {
                if (i == 0) {
                    // handled below with second loop struct
                }
            }
            break;  // restructure below
        }
        // NOTE: restructured loading (single sync before stores):
        {
            // A: 2 float4 per thread
            float4 av0 = make_float4(0.f,0.f,0.f,0.f), av1 = make_float4(0.f,0.f,0.f,0.f);
            int fid0 = tid * 2, fid1 = tid * 2 + 1;
            int r0 = fid0 >> 2, c40 = (fid0 & 3) * 4;
            int r1 = fid1 >> 2, c41 = (fid1 & 3) * 4;
            if (m0 + r0 < M) av0 = *(const float4*)(A + (size_t)(m0 + r0) * K + k0 + c40);
            if (m0 + r1 < M) av1 = *(const float4*)(A + (size_t)(m0 + r1) * K + k0 + c41);
            // B
            float4 bv0 = make_float4(0.f,0.f,0.f,0.f), bv1 = make_float4(0.f,0.f,0.f,0.f);
            int bkr0, bc0, bkr1 = 0, bc1 = 0;
            if (BN == 128) {
                int bf0 = tid * 2, bf1 = tid * 2 + 1;
                bkr0 = bf0 >> 5; bc0 = (bf0 & 31) * 4;
                bkr1 = bf1 >> 5; bc1 = (bf1 & 31) * 4;
                bv0 = *(const float4*)(B + (size_t)(k0 + bkr0) * Ncol + n0 + bc0);
                bv1 = *(const float4*)(B + (size_t)(k0 + bkr1) * Ncol + n0 + bc1);
            } else {
                bkr0 = tid >> 4; bc0 = (tid & 15) * 4;
                bv0 = *(const float4*)(B + (size_t)(k0 + bkr0) * Ncol + n0 + bc0);
            }
            __syncthreads();
            *(uint4*)&As[r0][c40] = make_uint4(f2tf32(av0.x), f2tf32(av0.y), f2tf32(av0.z), f2tf32(av0.w));
            *(uint4*)&As[r1][c41] = make_uint4(f2tf32(av1.x), f2tf32(av1.y), f2tf32(av1.z), f2tf32(av1.w));
            *(uint4*)&Bs[bkr0][bc0] = make_uint4(f2tf32(bv0.x), f2tf32(bv0.y), f2tf32(bv0.z), f2tf32(bv0.w));
            if (BN == 128)
                *(uint4*)&Bs[bkr1][bc1] = make_uint4(f2tf32(bv1.x), f2tf32(bv1.y), f2tf32(bv1.z), f2tf32(bv1.w));
            __syncthreads();
        }
#pragma unroll
        for (int ks = 0; ks < 16; ks += 8) {
            uint32_t a[2][4];
#pragma unroll
            for (int mf = 0; mf < 2; mf++) {
                int rb = warp_m * 32 + mf * 16;
                a[mf][0] = As[rb + g][ks + t4];
                a[mf][1] = As[rb + 8 + g][ks + t4];
                a[mf][2] = As[rb + g][ks + 4 + t4];
                a[mf][3] = As[rb + 8 + g][ks + 4 + t4];
            }
#pragma unroll
            for (int nf = 0; nf < NF; nf++) {
                int cb = warp_n * (BN / 2) + nf * 8;
                uint32_t b0 = Bs[ks + t4][cb + g];
                uint32_t b1 = Bs[ks + 4 + t4][cb + g];
#pragma unroll
                for (int mf = 0; mf < 2; mf++) {
                    asm volatile(
                        "mma.sync.aligned.m16n8k8.row.col.f32.tf32.tf32.f32 "
                        "{%0,%1,%2,%3}, {%4,%5,%6,%7}, {%8,%9}, {%0,%1,%2,%3};"
                        : "+f"(acc[mf][nf][0]), "+f"(acc[mf][nf][1]),
                          "+f"(acc[mf][nf][2]), "+f"(acc[mf][nf][3])
                        : "r"(a[mf][0]), "r"(a[mf][1]), "r"(a[mf][2]), "r"(a[mf][3]),
                          "r"(b0), "r"(b1));
                }
            }
        }
    }
    // epilogue
#pragma unroll
    for (int mf = 0; mf < 2; mf++) {
#pragma unroll
        for (int nf = 0; nf < NF; nf++) {
            int row0 = m0 + warp_m * 32 + mf * 16 + g;
            int col  = n0 + warp_n * (BN / 2) + nf * 8 + 2 * t4;
            if (row0 < M)
                *(float2*)(C + (size_t)row0 * Ncol + col) =
                    make_float2(acc[mf][nf][0], acc[mf][nf][1]);
            if (row0 + 8 < M)
                *(float2*)(C + (size_t)(row0 + 8) * Ncol + col) =
                    make_float2(acc[mf][nf][2], acc[mf][nf][3]);
        }
    }
}

__global__ void gemm1_kernel(const float* __restrict__ x, const float* __restrict__ W1) {
    gemm_tf32_body<128, FIN>(x, W1, g_h1, NN, C1);
}
__global__ void gemm2_kernel(const float* __restrict__ W2) {
    gemm_tf32_body<64, C1>(g_out1, W2, g_h2, NN, HIDD);
}

// ---------------- per-node attention logits, layer 1 (warp per node) ----------------
__global__ void logits1_kernel(const float* __restrict__ as1, const float* __restrict__ ad1) {
    int w = (blockIdx.x * blockDim.x + threadIdx.x) >> 5;
    int lane = threadIdx.x & 31;
    if (w >= NN) return;
    const float4* hp = (const float4*)(g_h1 + (size_t)w * C1);
    const float4* sp = (const float4*)as1;
    const float4* dp = (const float4*)ad1;
    float4 h0 = hp[lane * 2], h1v = hp[lane * 2 + 1];
    float4 s0 = sp[lane * 2], s1  = sp[lane * 2 + 1];
    float4 d0 = dp[lane * 2], d1  = dp[lane * 2 + 1];
    float ss = h0.x*s0.x + h0.y*s0.y + h0.z*s0.z + h0.w*s0.w
             + h1v.x*s1.x + h1v.y*s1.y + h1v.z*s1.z + h1v.w*s1.w;
    float dd = h0.x*d0.x + h0.y*d0.y + h0.z*d0.z + h0.w*d0.w
             + h1v.x*d1.x + h1v.y*d1.y + h1v.z*d1.z + h1v.w*d1.w;
    for (int o = 4; o; o >>= 1) {
        ss += __shfl_down_sync(0xffffffffu, ss, o, 8);
        dd += __shfl_down_sync(0xffffffffu, dd, o, 8);
    }
    if ((lane & 7) == 0) {
        g_als1[w * 4 + (lane >> 3)] = ss;
        g_ald1[w * 4 + (lane >> 3)] = dd;
    }
}

// ---- layer-1 aggregation (fused attention softmax): warp per dst node ----
__global__ void agg1_kernel(const float* __restrict__ b1) {
    int n = (blockIdx.x * blockDim.x + threadIdx.x) >> 5;
    int lane = threadIdx.x & 31;
    if (n >= NN) return;
    int beg = g_row[n], end = g_row[n + 1];
    int h = lane >> 3;
    float ald = g_ald1[n * 4 + h];
    float ce  = g_scal[1 + h];
    float4 acc0 = make_float4(0.f, 0.f, 0.f, 0.f);
    float4 acc1 = make_float4(0.f, 0.f, 0.f, 0.f);
    float den = 0.f;
    int j = beg;
    for (; j + 2 <= end; j += 2) {
        int2 se0 = g_elist[j];
        int2 se1 = g_elist[j + 1];
        float als0 = g_als1[se0.x * 4 + h];
        float als1v = g_als1[se1.x * 4 + h];
        const float4* sp0 = (const float4*)(g_h1 + (size_t)se0.x * C1);
        const float4* sp1 = (const float4*)(g_h1 + (size_t)se1.x * C1);
        float4 u0 = sp0[lane * 2], u1 = sp0[lane * 2 + 1];
        float4 v0 = sp1[lane * 2], v1 = sp1[lane * 2 + 1];
        float z0 = als0 + ald + __int_as_float(se0.y) * ce;
        float z1 = als1v + ald + __int_as_float(se1.y) * ce;
        z0 = z0 > 0.f ? z0 : 0.2f * z0;
        z1 = z1 > 0.f ? z1 : 0.2f * z1;
        float ex0 = expf(z0), ex1 = expf(z1);
        den += ex0 + ex1;
        acc0.x += ex0 * u0.x + ex1 * v0.x;
        acc0.y += ex0 * u0.y + ex1 * v0.y;
        acc0.z += ex0 * u0.z + ex1 * v0.z;
        acc0.w += ex0 * u0.w + ex1 * v0.w;
        acc1.x += ex0 * u1.x + ex1 * v1.x;
        acc1.y += ex0 * u1.y + ex1 * v1.y;
        acc1.z += ex0 * u1.z + ex1 * v1.z;
        acc1.w += ex0 * u1.w + ex1 * v1.w;
    }
    if (j < end) {
        int2 se = g_elist[j];
        float als = g_als1[se.x * 4 + h];
        const float4* sp = (const float4*)(g_h1 + (size_t)se.x * C1);
        float4 u0 = sp[lane * 2], u1 = sp[lane * 2 + 1];
        float z = als + ald + __int_as_float(se.y) * ce;
        z = z > 0.f ? z : 0.2f * z;
        float ex = expf(z);
        den += ex;
        acc0.x += ex * u0.x; acc0.y += ex * u0.y; acc0.z += ex * u0.z; acc0.w += ex * u0.w;
        acc1.x += ex * u1.x; acc1.y += ex * u1.y; acc1.z += ex * u1.z; acc1.w += ex * u1.w;
    }
    float inv = 1.f / (den + 1e-16f);
    const float4* bp = (const float4*)b1;
    float4 bb0 = bp[lane * 2], bb1 = bp[lane * 2 + 1];
    float4 o0, o1;
    o0.x = fmaxf(acc0.x * inv + bb0.x, 0.f);
    o0.y = fmaxf(acc0.y * inv + bb0.y, 0.f);
    o0.z = fmaxf(acc0.z * inv + bb0.z, 0.f);
    o0.w = fmaxf(acc0.w * inv + bb0.w, 0.f);
    o1.x = fmaxf(acc1.x * inv + bb1.x, 0.f);
    o1.y = fmaxf(acc1.y * inv + bb1.y, 0.f);
    o1.z = fmaxf(acc1.z * inv + bb1.z, 0.f);
    o1.w = fmaxf(acc1.w * inv + bb1.w, 0.f);
    float4* op = (float4*)(g_out1 + (size_t)n * C1);
    op[lane * 2] = o0;
    op[lane * 2 + 1] = o1;
}

// ---------------- per-node logits, layer 2 (warp per node) ----------------
__global__ void logits2_kernel(const float* __restrict__ as2, const float* __restrict__ ad2) {
    int w = (blockIdx.x * blockDim.x + threadIdx.x) >> 5;
    int lane = threadIdx.x & 31;
    if (w >= NN) return;
    float2 v = ((const float2*)(g_h2 + (size_t)w * HIDD))[lane];
    float2 s = ((const float2*)as2)[lane];
    float2 dv = ((const float2*)ad2)[lane];
    float ss = v.x * s.x + v.y * s.y;
    float dd = v.x * dv.x + v.y * dv.y;
    for (int o = 16; o; o >>= 1) {
        ss += __shfl_xor_sync(0xffffffffu, ss, o);
        dd += __shfl_xor_sync(0xffffffffu, dd, o);
    }
    if (lane == 0) { g_als2[w] = ss; g_ald2[w] = dd; }
}

// ---- layer-2 aggregation (fused attention) + bias + LayerNorm + pool ----
__global__ void agg2_ln_pool_kernel(const float* __restrict__ b2,
                                    const float* __restrict__ lng,
                                    const float* __restrict__ lnb,
                                    const int* __restrict__ batch) {
    int n = (blockIdx.x * blockDim.x + threadIdx.x) >> 5;
    int lane = threadIdx.x & 31;
    if (n >= NN) return;
    int beg = g_row[n], end = g_row[n + 1];
    float ald = g_ald2[n];
    float ce  = g_scal[5];
    float2 acc = make_float2(0.f, 0.f);
    float den = 0.f;
    int j = beg;
    for (; j + 2 <= end; j += 2) {
        int2 se0 = g_elist[j];
        int2 se1 = g_elist[j + 1];
        float als0 = g_als2[se0.x];
        float als1v = g_als2[se1.x];
        float2 u = ((const float2*)(g_h2 + (size_t)se0.x * HIDD))[lane];
        float2 v = ((const float2*)(g_h2 + (size_t)se1.x * HIDD))[lane];
        float z0 = als0 + ald + __int_as_float(se0.y) * ce;
        float z1 = als1v + ald + __int_as_float(se1.y) * ce;
        z0 = z0 > 0.f ? z0 : 0.2f * z0;
        z1 = z1 > 0.f ? z1 : 0.2f * z1;
        float ex0 = expf(z0), ex1 = expf(z1);
        den += ex0 + ex1;
        acc.x += ex0 * u.x + ex1 * v.x;
        acc.y += ex0 * u.y + ex1 * v.y;
    }
    if (j < end) {
        int2 se = g_elist[j];
        float als = g_als2[se.x];
        float2 u = ((const float2*)(g_h2 + (size_t)se.x * HIDD))[lane];
        float z = als + ald + __int_as_float(se.y) * ce;
        z = z > 0.f ? z : 0.2f * z;
        float ex = expf(z);
        den += ex;
        acc.x += ex * u.x;
        acc.y += ex * u.y;
    }
    float inv = 1.f / (den + 1e-16f);
    float2 bb = ((const float2*)b2)[lane];
    float vx = acc.x * inv + bb.x;
    float vy = acc.y * inv + bb.y;
    float s = vx + vy;
    for (int o = 16; o; o >>= 1) s += __shfl_xor_sync(0xffffffffu, s, o);
    float mu = s * (1.0f / 64.0f);
    float dx = vx - mu, dy = vy - mu;
    float q = dx * dx + dy * dy;
    for (int o = 16; o; o >>= 1) q += __shfl_xor_sync(0xffffffffu, q, o);
    float r = rsqrtf(q * (1.0f / 64.0f) + 1e-5f);
    float y0 = dx * r * lng[lane * 2]     + lnb[lane * 2];
    float y1 = dy * r * lng[lane * 2 + 1] + lnb[lane * 2 + 1];
    int g = batch[n];
    atomicAdd(&g_sums[g * 64 + lane * 2],     y0);
    atomicAdd(&g_sums[g * 64 + lane * 2 + 1], y1);
    if (lane == 0) atomicAdd(&g_cnt[g], 1.0f);
}

// ---------------- per-graph MLP head (block per graph, 64 threads) ----------------
__global__ void mlp_kernel(const float* __restrict__ clin, const float* __restrict__ met,
                           const float* __restrict__ Wf1, const float* __restrict__ bf1,
                           const float* __restrict__ Wf2, const float* __restrict__ bf2,
                           const float* __restrict__ Wr,  const float* __restrict__ br,
                           float* __restrict__ out) {
    int g = blockIdx.x, t = threadIdx.x;   // 64 threads
    __shared__ float fused[FUSED_IN];
    __shared__ float l1[64];
    __shared__ float l2[32];
    float cnt = g_cnt[g]; cnt = cnt > 1.f ? cnt : 1.f;
    float e = g_sums[g * 64 + t] / cnt;
    fused[t] = e;
    out[GG + g * 64 + t] = e;              // graph_embedding at offset 64
    if (t < 32) fused[64 + t] = clin[g * 32 + t];
    fused[96 + t]  = met[g * 128 + t];
    fused[160 + t] = met[g * 128 + 64 + t];
    __syncthreads();
    float acc = bf1[t];
#pragma unroll 8
    for (int k = 0; k < FUSED_IN; k++) acc += fused[k] * Wf1[k * 64 + t];
    l1[t] = acc > 0.f ? acc : 0.f;
    __syncthreads();
    if (t < 32) {
        float a2 = bf2[t];
#pragma unroll 8
        for (int j = 0; j < 64; j++) a2 += l1[j] * Wf2[j * 32 + t];
        a2 = a2 > 0.f ? a2 : 0.f;
        l2[t] = a2;
        out[GG + GG * 64 + g * 32 + t] = a2;   // latent at offset 64 + 4096
    }
    __syncthreads();
    if (t == 0) {
        float r = br[0];
#pragma unroll
        for (int j = 0; j < 32; j++) r += l2[j] * Wr[j];
        out[g] = r;                        // risk at offset 0
    }
}

// ---------------- launch ----------------
extern "C" void kernel_launch(void* const* d_in, const int* in_sizes, int n_in,
                              void* d_out, int out_size) {
    const float* x    = (const float*)d_in[0];
    const int*   ei   = (const int*)d_in[1];
    const float* ea   = (const float*)d_in[2];
    const int*   bat  = (const int*)d_in[3];
    const float* clin = (const float*)d_in[4];
    const float* met  = (const float*)d_in[5];
    const float* W1   = (const float*)d_in[6];
    const float* as1  = (const float*)d_in[7];
    const float* ad1  = (const float*)d_in[8];
    const float* ae1  = (const float*)d_in[9];
    const float* We1  = (const float*)d_in[10];
    const float* b1   = (const float*)d_in[11];
    const float* W2   = (const float*)d_in[12];
    const float* as2  = (const float*)d_in[13];
    const float* ad2  = (const float*)d_in[14];
    const float* ae2  = (const float*)d_in[15];
    const float* We2  = (const float*)d_in[16];
    const float* b2   = (const float*)d_in[17];
    const float* lng  = (const float*)d_in[18];
    const float* lnb  = (const float*)d_in[19];
    const float* Wf1  = (const float*)d_in[20];
    const float* bf1  = (const float*)d_in[21];
    const float* Wf2  = (const float*)d_in[22];
    const float* bf2  = (const float*)d_in[23];
    const float* Wr   = (const float*)d_in[24];
    const float* br   = (const float*)d_in[25];
    float* out = (float*)d_out;

    zero_small_kernel<<<(NN + 255) / 256, 256>>>();     // 0
    mean_ea_kernel<<<512, 256>>>(ea);                   // 1
    ce_kernel<<<1, 256>>>(We1, ae1, We2, ae2);          // 2

    // layer-1 GEMM first (independent of CSR) -> lands at ncu capture index 3
    gemm1_kernel<<<dim3(C1 / 128, (NN + 127) / 128), 256>>>(x, W1);   // 3

    // CSR build (by dst), with edge_attr fused into the list
    hist_kernel<<<(ELOOP + 255) / 256, 256>>>(ei);      // 4
    scan_kernel<<<1, 1024>>>();                         // 5
    scatter_kernel<<<(ELOOP + 255) / 256, 256>>>(ei, ea); // 6

    // layer 1
    logits1_kernel<<<(NN * 32 + 255) / 256, 256>>>(as1, ad1);
    agg1_kernel<<<(NN * 32 + 255) / 256, 256>>>(b1);

    // layer 2
    gemm2_kernel<<<dim3(1, (NN + 127) / 128), 256>>>(W2);
    logits2_kernel<<<(NN * 32 + 255) / 256, 256>>>(as2, ad2);
    agg2_ln_pool_kernel<<<(NN * 32 + 255) / 256, 256>>>(b2, lng, lnb, bat);

    // head
    mlp_kernel<<<GG, 64>>>(clin, met, Wf1, bf1, Wf2, bf2, Wr, br, out);
}

// round 7
// speedup vs baseline: 4.1174x; 1.0918x over previous
#include <cuda_runtime.h>
#include <cstdint>

// ---------------- fixed problem shapes ----------------
#define NN      50000
#define EE      800000
#define ELOOP   850000        // EE + NN self loops
#define GG      64
#define FIN     128
#define HIDD    64
#define HEADS   4
#define C1      256           // HEADS*HIDD
#define CLIN    32
#define MET     128
#define FUSED_IN 224          // HIDD + CLIN + MET

// ---------------- device scratch (no allocs allowed) ----------------
__device__ float g_h1  [(size_t)NN * C1];     // x @ W1
__device__ float g_out1[(size_t)NN * C1];     // layer1 output (post bias+relu)
__device__ float g_h2  [(size_t)NN * HIDD];   // out1 @ W2
__device__ float g_als1[NN * HEADS];
__device__ float g_ald1[NN * HEADS];
__device__ float g_als2[NN];
__device__ float g_ald2[NN];
__device__ float g_sums[GG * HIDD];
__device__ float g_cnt [GG];
__device__ float g_scal[8];     // [0]=sum(edge_attr), [1..4]=ce1[h], [5]=ce2
__device__ float g_part[512];   // per-block partial sums of edge_attr
// CSR by destination
__device__ int  g_row [NN + 1];
__device__ int  g_cur [NN];     // hist -> cursor
__device__ int2 g_elist[ELOOP]; // (src, float_bits(edge_attr)) sorted by dst

// ---------------- prep: zero scratch + partial sums of edge_attr ----------------
// grid 512 x 256 (131072 threads >= NN)
__global__ void prep_kernel(const float* __restrict__ ea) {
    __shared__ float sh[8];
    int i = blockIdx.x * blockDim.x + threadIdx.x;
    if (i < NN) g_cur[i] = 0;
    if (i < GG * HIDD) g_sums[i] = 0.f;
    if (i < GG) g_cnt[i] = 0.f;
    if (i < 8)  g_scal[i] = 0.f;
    float s = 0.f;
    for (size_t e = i; e < EE; e += (size_t)512 * 256) s += ea[e];
    for (int o = 16; o; o >>= 1) s += __shfl_xor_sync(0xffffffffu, s, o);
    if ((threadIdx.x & 31) == 0) sh[threadIdx.x >> 5] = s;
    __syncthreads();
    if (threadIdx.x < 8) {
        float v = sh[threadIdx.x];
        for (int o = 4; o; o >>= 1) v += __shfl_xor_sync(0xffu, v, o);
        if (threadIdx.x == 0) g_part[blockIdx.x] = v;
    }
}

// ---------------- CSR build: histogram of dst ----------------
__global__ void hist_kernel(const int* __restrict__ ei) {
    int e = blockIdx.x * blockDim.x + threadIdx.x;
    if (e >= ELOOP) return;
    int d = (e < EE) ? ei[EE + e] : (e - EE);
    atomicAdd(&g_cur[d], 1);
}

// ------- scan (single block, 1024 thr): finalize mean + ce dots + exclusive scan -------
#define CHUNK 49   // 1024*49 = 50176 >= NN
__global__ void scan_kernel(const float* __restrict__ We1, const float* __restrict__ ae1,
                            const float* __restrict__ We2, const float* __restrict__ ae2) {
    __shared__ int ps[1024];
    __shared__ float fs[32];
    int t = threadIdx.x;
    int lane = t & 31, warp = t >> 5;
    // finalize sum(edge_attr) into g_scal[0]
    float v = (t < 512) ? g_part[t] : 0.f;
    for (int o = 16; o; o >>= 1) v += __shfl_xor_sync(0xffffffffu, v, o);
    if (lane == 0) fs[warp] = v;
    __syncthreads();
    if (t < 32) {
        float u = fs[t];
        for (int o = 16; o; o >>= 1) u += __shfl_xor_sync(0xffffffffu, u, o);
        if (t == 0) g_scal[0] = u;
    }
    // ce dots (scal[1..5] zeroed by prep)
    if (t < C1) atomicAdd(&g_scal[1 + (t >> 6)], We1[t] * ae1[t]);
    if (t < 64) atomicAdd(&g_scal[5], We2[t] * ae2[t]);
    // exclusive scan of degrees
    int base = t * CHUNK;
    int s = 0;
    for (int i = 0; i < CHUNK; i++) {
        int idx = base + i;
        if (idx < NN) s += g_cur[idx];
    }
    ps[t] = s;
    __syncthreads();
    for (int off = 1; off < 1024; off <<= 1) {
        int w = (t >= off) ? ps[t - off] : 0;
        __syncthreads();
        ps[t] += w;
        __syncthreads();
    }
    int run = ps[t] - s;
    for (int i = 0; i < CHUNK; i++) {
        int idx = base + i;
        if (idx < NN) {
            int d = g_cur[idx];
            g_row[idx] = run;
            g_cur[idx] = run;
            run += d;
        }
    }
    if (t == 0) g_row[NN] = ELOOP;
}

// ---------------- CSR build: scatter (src, edge_attr) ----------------
__global__ void scatter_kernel(const int* __restrict__ ei, const float* __restrict__ ea) {
    int e = blockIdx.x * blockDim.x + threadIdx.x;
    if (e >= ELOOP) return;
    int s, d; float att;
    if (e < EE) { s = ei[e]; d = ei[EE + e]; att = ea[e]; }
    else        { s = d = e - EE; att = g_scal[0] * (1.0f / EE); }
    int pos = atomicAdd(&g_cur[d], 1);
    g_elist[pos] = make_int2(s, __float_as_int(att));
}

// ---------------- TF32 tensor-core GEMM, double-buffered ----------------
// C[M,Ncol] = A[M,K] @ B[K,Ncol], row-major. BM=128, BK=16, 256 threads (8 warps, 4x2).
// Raw fp32 bits fed to mma.tf32 (HW truncates mantissa).
template<int BN, int K>
__device__ __forceinline__ void gemm_tf32_body(const float* __restrict__ A,
                                               const float* __restrict__ B,
                                               float* __restrict__ C,
                                               int M, int Ncol) {
    constexpr int NF = BN / 16;              // n-fragments per warp (8 or 4)
    __shared__ uint32_t As[2][128][20];
    __shared__ uint32_t Bs[2][16][BN + 8];   // stride BN+8: conflict-free (g + 8*t4)
    int tid = threadIdx.x;
    int warp = tid >> 5, lane = tid & 31;
    int warp_m = warp & 3;                   // 32 rows each
    int warp_n = warp >> 2;                  // BN/2 cols each
    int m0 = blockIdx.y * 128, n0 = blockIdx.x * BN;
    int g = lane >> 2, t4 = lane & 3;

    // loader indices
    int arow = tid >> 1, acb = (tid & 1) * 8;         // A: row, 8 floats
    int brow = tid >> 4;                               // B row
    int bcb  = (BN == 128) ? (tid & 15) * 8 : (tid & 15) * 4;

    float acc[2][NF][4];
#pragma unroll
    for (int mf = 0; mf < 2; mf++)
#pragma unroll
        for (int nf = 0; nf < NF; nf++)
#pragma unroll
            for (int i = 0; i < 4; i++) acc[mf][nf][i] = 0.f;

    float4 pa0, pa1, pb0, pb1;
    auto load_tile = [&](int k0) {
        pa0 = make_float4(0.f, 0.f, 0.f, 0.f);
        pa1 = make_float4(0.f, 0.f, 0.f, 0.f);
        if (m0 + arow < M) {
            const float* p = A + (size_t)(m0 + arow) * K + k0 + acb;
            pa0 = *(const float4*)p;
            pa1 = *(const float4*)(p + 4);
        }
        const float* q = B + (size_t)(k0 + brow) * Ncol + n0 + bcb;
        pb0 = *(const float4*)q;
        if (BN == 128) pb1 = *(const float4*)(q + 4);
    };
    auto store_tile = [&](int buf) {
        *(uint4*)&As[buf][arow][acb]     = *reinterpret_cast<uint4*>(&pa0);
        *(uint4*)&As[buf][arow][acb + 4] = *reinterpret_cast<uint4*>(&pa1);
        *(uint4*)&Bs[buf][brow][bcb]     = *reinterpret_cast<uint4*>(&pb0);
        if (BN == 128)
            *(uint4*)&Bs[buf][brow][bcb + 4] = *reinterpret_cast<uint4*>(&pb1);
    };
    auto compute = [&](int buf) {
#pragma unroll
        for (int ks = 0; ks < 16; ks += 8) {
            uint32_t a[2][4];
#pragma unroll
            for (int mf = 0; mf < 2; mf++) {
                int rb = warp_m * 32 + mf * 16;
                a[mf][0] = As[buf][rb + g][ks + t4];
                a[mf][1] = As[buf][rb + 8 + g][ks + t4];
                a[mf][2] = As[buf][rb + g][ks + 4 + t4];
                a[mf][3] = As[buf][rb + 8 + g][ks + 4 + t4];
            }
#pragma unroll
            for (int nf = 0; nf < NF; nf++) {
                int cb = warp_n * (BN / 2) + nf * 8;
                uint32_t b0 = Bs[buf][ks + t4][cb + g];
                uint32_t b1 = Bs[buf][ks + 4 + t4][cb + g];
#pragma unroll
                for (int mf = 0; mf < 2; mf++) {
                    asm volatile(
                        "mma.sync.aligned.m16n8k8.row.col.f32.tf32.tf32.f32 "
                        "{%0,%1,%2,%3}, {%4,%5,%6,%7}, {%8,%9}, {%0,%1,%2,%3};"
                        : "+f"(acc[mf][nf][0]), "+f"(acc[mf][nf][1]),
                          "+f"(acc[mf][nf][2]), "+f"(acc[mf][nf][3])
                        : "r"(a[mf][0]), "r"(a[mf][1]), "r"(a[mf][2]), "r"(a[mf][3]),
                          "r"(b0), "r"(b1));
                }
            }
        }
    };

    load_tile(0);
    store_tile(0);
    __syncthreads();
    int cur = 0;
    for (int k0 = 0; k0 < K; k0 += 16) {
        bool more = (k0 + 16 < K);
        if (more) load_tile(k0 + 16);
        compute(cur);
        if (more) store_tile(cur ^ 1);
        __syncthreads();
        cur ^= 1;
    }

    // epilogue
#pragma unroll
    for (int mf = 0; mf < 2; mf++) {
#pragma unroll
        for (int nf = 0; nf < NF; nf++) {
            int row0 = m0 + warp_m * 32 + mf * 16 + g;
            int col  = n0 + warp_n * (BN / 2) + nf * 8 + 2 * t4;
            if (row0 < M)
                *(float2*)(C + (size_t)row0 * Ncol + col) =
                    make_float2(acc[mf][nf][0], acc[mf][nf][1]);
            if (row0 + 8 < M)
                *(float2*)(C + (size_t)(row0 + 8) * Ncol + col) =
                    make_float2(acc[mf][nf][2], acc[mf][nf][3]);
        }
    }
}

__global__ void gemm1_kernel(const float* __restrict__ x, const float* __restrict__ W1) {
    gemm_tf32_body<128, FIN>(x, W1, g_h1, NN, C1);
}
__global__ void gemm2_kernel(const float* __restrict__ W2) {
    gemm_tf32_body<64, C1>(g_out1, W2, g_h2, NN, HIDD);
}

// ---------------- per-node attention logits, layer 1 (warp per node) ----------------
__global__ void logits1_kernel(const float* __restrict__ as1, const float* __restrict__ ad1) {
    int w = (blockIdx.x * blockDim.x + threadIdx.x) >> 5;
    int lane = threadIdx.x & 31;
    if (w >= NN) return;
    const float4* hp = (const float4*)(g_h1 + (size_t)w * C1);
    const float4* sp = (const float4*)as1;
    const float4* dp = (const float4*)ad1;
    float4 h0 = hp[lane * 2], h1v = hp[lane * 2 + 1];
    float4 s0 = sp[lane * 2], s1  = sp[lane * 2 + 1];
    float4 d0 = dp[lane * 2], d1  = dp[lane * 2 + 1];
    float ss = h0.x*s0.x + h0.y*s0.y + h0.z*s0.z + h0.w*s0.w
             + h1v.x*s1.x + h1v.y*s1.y + h1v.z*s1.z + h1v.w*s1.w;
    float dd = h0.x*d0.x + h0.y*d0.y + h0.z*d0.z + h0.w*d0.w
             + h1v.x*d1.x + h1v.y*d1.y + h1v.z*d1.z + h1v.w*d1.w;
    for (int o = 4; o; o >>= 1) {
        ss += __shfl_down_sync(0xffffffffu, ss, o, 8);
        dd += __shfl_down_sync(0xffffffffu, dd, o, 8);
    }
    if ((lane & 7) == 0) {
        g_als1[w * 4 + (lane >> 3)] = ss;
        g_ald1[w * 4 + (lane >> 3)] = dd;
    }
}

// ---- layer-1 aggregation (fused attention softmax): warp per dst node, unroll 4 ----
__global__ void agg1_kernel(const float* __restrict__ b1) {
    int n = (blockIdx.x * blockDim.x + threadIdx.x) >> 5;
    int lane = threadIdx.x & 31;
    if (n >= NN) return;
    int beg = g_row[n], end = g_row[n + 1];
    int h = lane >> 3;
    float ald = g_ald1[n * 4 + h];
    float ce  = g_scal[1 + h];
    float4 acc0 = make_float4(0.f, 0.f, 0.f, 0.f);
    float4 acc1 = make_float4(0.f, 0.f, 0.f, 0.f);
    float den = 0.f;
    int j = beg;
    for (; j + 4 <= end; j += 4) {
        int2 se[4];
#pragma unroll
        for (int q = 0; q < 4; q++) se[q] = g_elist[j + q];
        float ex[4];
        float4 u0[4], u1[4];
#pragma unroll
        for (int q = 0; q < 4; q++) {
            const float4* sp = (const float4*)(g_h1 + (size_t)se[q].x * C1);
            u0[q] = sp[lane * 2];
            u1[q] = sp[lane * 2 + 1];
            float z = g_als1[se[q].x * 4 + h] + ald + __int_as_float(se[q].y) * ce;
            z = z > 0.f ? z : 0.2f * z;
            ex[q] = expf(z);
        }
#pragma unroll
        for (int q = 0; q < 4; q++) {
            den += ex[q];
            acc0.x += ex[q] * u0[q].x; acc0.y += ex[q] * u0[q].y;
            acc0.z += ex[q] * u0[q].z; acc0.w += ex[q] * u0[q].w;
            acc1.x += ex[q] * u1[q].x; acc1.y += ex[q] * u1[q].y;
            acc1.z += ex[q] * u1[q].z; acc1.w += ex[q] * u1[q].w;
        }
    }
    for (; j < end; j++) {
        int2 se = g_elist[j];
        const float4* sp = (const float4*)(g_h1 + (size_t)se.x * C1);
        float4 u0 = sp[lane * 2], u1 = sp[lane * 2 + 1];
        float z = g_als1[se.x * 4 + h] + ald + __int_as_float(se.y) * ce;
        z = z > 0.f ? z : 0.2f * z;
        float ex = expf(z);
        den += ex;
        acc0.x += ex * u0.x; acc0.y += ex * u0.y; acc0.z += ex * u0.z; acc0.w += ex * u0.w;
        acc1.x += ex * u1.x; acc1.y += ex * u1.y; acc1.z += ex * u1.z; acc1.w += ex * u1.w;
    }
    float inv = 1.f / (den + 1e-16f);
    const float4* bp = (const float4*)b1;
    float4 bb0 = bp[lane * 2], bb1 = bp[lane * 2 + 1];
    float4 o0, o1;
    o0.x = fmaxf(acc0.x * inv + bb0.x, 0.f);
    o0.y = fmaxf(acc0.y * inv + bb0.y, 0.f);
    o0.z = fmaxf(acc0.z * inv + bb0.z, 0.f);
    o0.w = fmaxf(acc0.w * inv + bb0.w, 0.f);
    o1.x = fmaxf(acc1.x * inv + bb1.x, 0.f);
    o1.y = fmaxf(acc1.y * inv + bb1.y, 0.f);
    o1.z = fmaxf(acc1.z * inv + bb1.z, 0.f);
    o1.w = fmaxf(acc1.w * inv + bb1.w, 0.f);
    float4* op = (float4*)(g_out1 + (size_t)n * C1);
    op[lane * 2] = o0;
    op[lane * 2 + 1] = o1;
}

// ---------------- per-node logits, layer 2 (warp per node) ----------------
__global__ void logits2_kernel(const float* __restrict__ as2, const float* __restrict__ ad2) {
    int w = (blockIdx.x * blockDim.x + threadIdx.x) >> 5;
    int lane = threadIdx.x & 31;
    if (w >= NN) return;
    float2 v = ((const float2*)(g_h2 + (size_t)w * HIDD))[lane];
    float2 s = ((const float2*)as2)[lane];
    float2 dv = ((const float2*)ad2)[lane];
    float ss = v.x * s.x + v.y * s.y;
    float dd = v.x * dv.x + v.y * dv.y;
    for (int o = 16; o; o >>= 1) {
        ss += __shfl_xor_sync(0xffffffffu, ss, o);
        dd += __shfl_xor_sync(0xffffffffu, dd, o);
    }
    if (lane == 0) { g_als2[w] = ss; g_ald2[w] = dd; }
}

// ---- layer-2 aggregation (fused attention) + bias + LayerNorm + pool, unroll 4 ----
__global__ void agg2_ln_pool_kernel(const float* __restrict__ b2,
                                    const float* __restrict__ lng,
                                    const float* __restrict__ lnb,
                                    const int* __restrict__ batch) {
    int n = (blockIdx.x * blockDim.x + threadIdx.x) >> 5;
    int lane = threadIdx.x & 31;
    if (n >= NN) return;
    int beg = g_row[n], end = g_row[n + 1];
    float ald = g_ald2[n];
    float ce  = g_scal[5];
    float2 acc = make_float2(0.f, 0.f);
    float den = 0.f;
    int j = beg;
    for (; j + 4 <= end; j += 4) {
        int2 se[4];
#pragma unroll
        for (int q = 0; q < 4; q++) se[q] = g_elist[j + q];
        float ex[4];
        float2 u[4];
#pragma unroll
        for (int q = 0; q < 4; q++) {
            u[q] = ((const float2*)(g_h2 + (size_t)se[q].x * HIDD))[lane];
            float z = g_als2[se[q].x] + ald + __int_as_float(se[q].y) * ce;
            z = z > 0.f ? z : 0.2f * z;
            ex[q] = expf(z);
        }
#pragma unroll
        for (int q = 0; q < 4; q++) {
            den += ex[q];
            acc.x += ex[q] * u[q].x;
            acc.y += ex[q] * u[q].y;
        }
    }
    for (; j < end; j++) {
        int2 se = g_elist[j];
        float2 u = ((const float2*)(g_h2 + (size_t)se.x * HIDD))[lane];
        float z = g_als2[se.x] + ald + __int_as_float(se.y) * ce;
        z = z > 0.f ? z : 0.2f * z;
        float ex = expf(z);
        den += ex;
        acc.x += ex * u.x;
        acc.y += ex * u.y;
    }
    float inv = 1.f / (den + 1e-16f);
    float2 bb = ((const float2*)b2)[lane];
    float vx = acc.x * inv + bb.x;
    float vy = acc.y * inv + bb.y;
    float s = vx + vy;
    for (int o = 16; o; o >>= 1) s += __shfl_xor_sync(0xffffffffu, s, o);
    float mu = s * (1.0f / 64.0f);
    float dx = vx - mu, dy = vy - mu;
    float q = dx * dx + dy * dy;
    for (int o = 16; o; o >>= 1) q += __shfl_xor_sync(0xffffffffu, q, o);
    float r = rsqrtf(q * (1.0f / 64.0f) + 1e-5f);
    float y0 = dx * r * lng[lane * 2]     + lnb[lane * 2];
    float y1 = dy * r * lng[lane * 2 + 1] + lnb[lane * 2 + 1];
    int g = batch[n];
    atomicAdd(&g_sums[g * 64 + lane * 2],     y0);
    atomicAdd(&g_sums[g * 64 + lane * 2 + 1], y1);
    if (lane == 0) atomicAdd(&g_cnt[g], 1.0f);
}

// ---------------- per-graph MLP head (block per graph, 64 threads) ----------------
__global__ void mlp_kernel(const float* __restrict__ clin, const float* __restrict__ met,
                           const float* __restrict__ Wf1, const float* __restrict__ bf1,
                           const float* __restrict__ Wf2, const float* __restrict__ bf2,
                           const float* __restrict__ Wr,  const float* __restrict__ br,
                           float* __restrict__ out) {
    int g = blockIdx.x, t = threadIdx.x;   // 64 threads
    __shared__ float fused[FUSED_IN];
    __shared__ float l1[64];
    __shared__ float l2[32];
    float cnt = g_cnt[g]; cnt = cnt > 1.f ? cnt : 1.f;
    float e = g_sums[g * 64 + t] / cnt;
    fused[t] = e;
    out[GG + g * 64 + t] = e;              // graph_embedding at offset 64
    if (t < 32) fused[64 + t] = clin[g * 32 + t];
    fused[96 + t]  = met[g * 128 + t];
    fused[160 + t] = met[g * 128 + 64 + t];
    __syncthreads();
    float acc = bf1[t];
#pragma unroll 8
    for (int k = 0; k < FUSED_IN; k++) acc += fused[k] * Wf1[k * 64 + t];
    l1[t] = acc > 0.f ? acc : 0.f;
    __syncthreads();
    if (t < 32) {
        float a2 = bf2[t];
#pragma unroll 8
        for (int j = 0; j < 64; j++) a2 += l1[j] * Wf2[j * 32 + t];
        a2 = a2 > 0.f ? a2 : 0.f;
        l2[t] = a2;
        out[GG + GG * 64 + g * 32 + t] = a2;   // latent at offset 64 + 4096
    }
    __syncthreads();
    if (t == 0) {
        float r = br[0];
#pragma unroll
        for (int j = 0; j < 32; j++) r += l2[j] * Wr[j];
        out[g] = r;                        // risk at offset 0
    }
}

// ---------------- launch ----------------
extern "C" void kernel_launch(void* const* d_in, const int* in_sizes, int n_in,
                              void* d_out, int out_size) {
    const float* x    = (const float*)d_in[0];
    const int*   ei   = (const int*)d_in[1];
    const float* ea   = (const float*)d_in[2];
    const int*   bat  = (const int*)d_in[3];
    const float* clin = (const float*)d_in[4];
    const float* met  = (const float*)d_in[5];
    const float* W1   = (const float*)d_in[6];
    const float* as1  = (const float*)d_in[7];
    const float* ad1  = (const float*)d_in[8];
    const float* ae1  = (const float*)d_in[9];
    const float* We1  = (const float*)d_in[10];
    const float* b1   = (const float*)d_in[11];
    const float* W2   = (const float*)d_in[12];
    const float* as2  = (const float*)d_in[13];
    const float* ad2  = (const float*)d_in[14];
    const float* ae2  = (const float*)d_in[15];
    const float* We2  = (const float*)d_in[16];
    const float* b2   = (const float*)d_in[17];
    const float* lng  = (const float*)d_in[18];
    const float* lnb  = (const float*)d_in[19];
    const float* Wf1  = (const float*)d_in[20];
    const float* bf1  = (const float*)d_in[21];
    const float* Wf2  = (const float*)d_in[22];
    const float* bf2  = (const float*)d_in[23];
    const float* Wr   = (const float*)d_in[24];
    const float* br   = (const float*)d_in[25];
    float* out = (float*)d_out;

    prep_kernel<<<512, 256>>>(ea);                          // 0
    hist_kernel<<<(ELOOP + 255) / 256, 256>>>(ei);          // 1
    scan_kernel<<<1, 1024>>>(We1, ae1, We2, ae2);           // 2
    gemm1_kernel<<<dim3(C1 / 128, (NN + 127) / 128), 256>>>(x, W1);  // 3 (profiled slot)
    scatter_kernel<<<(ELOOP + 255) / 256, 256>>>(ei, ea);   // 4

    // layer 1
    logits1_kernel<<<(NN * 32 + 255) / 256, 256>>>(as1, ad1);
    agg1_kernel<<<(NN * 32 + 255) / 256, 256>>>(b1);

    // layer 2
    gemm2_kernel<<<dim3(1, (NN + 127) / 128), 256>>>(W2);
    logits2_kernel<<<(NN * 32 + 255) / 256, 256>>>(as2, ad2);
    agg2_ln_pool_kernel<<<(NN * 32 + 255) / 256, 256>>>(b2, lng, lnb, bat);

    // head
    mlp_kernel<<<GG, 64>>>(clin, met, Wf1, bf1, Wf2, bf2, Wr, br, out);
}

// round 8
// speedup vs baseline: 4.5905x; 1.1149x over previous
#include <cuda_runtime.h>
#include <cuda_bf16.h>
#include <cstdint>

// ---------------- fixed problem shapes ----------------
#define NN      50000
#define EE      800000
#define ELOOP   850000        // EE + NN self loops
#define GG      64
#define FIN     128
#define HIDD    64
#define HEADS   4
#define C1      256           // HEADS*HIDD
#define CLIN    32
#define MET     128
#define FUSED_IN 224          // HID + CLIN + MET

// ---------------- device scratch (no allocs allowed) ----------------
__device__ float    g_h1  [(size_t)NN * C1];    // x @ W1 (fp32, for logits)
__device__ uint32_t g_h1b [(size_t)NN * (C1/2)];// bf16x2 packed copy (for agg gather)
__device__ float    g_out1[(size_t)NN * C1];    // layer1 output (post bias+relu)
__device__ float    g_h2  [(size_t)NN * HIDD];  // out1 @ W2 (fp32, for logits)
__device__ uint32_t g_h2b [(size_t)NN * (HIDD/2)];
__device__ float g_als1[NN * HEADS];
__device__ float g_ald1[NN * HEADS];
__device__ float g_als2[NN];
__device__ float g_ald2[NN];
__device__ float g_sums[GG * HIDD];
__device__ float g_cnt [GG];
__device__ float g_scal[8];     // [0]=sum(edge_attr), [1..4]=ce1[h], [5]=ce2
__device__ float g_part[512];   // per-block partial sums of edge_attr
// CSR by destination
__device__ int  g_row [NN + 1];
__device__ int  g_cur [NN];     // hist -> cursor
__device__ int2 g_elist[ELOOP]; // (src, float_bits(edge_attr)) sorted by dst

__device__ __forceinline__ uint32_t pack_bf16(float a, float b) {
    __nv_bfloat162 h = __float22bfloat162_rn(make_float2(a, b));
    return *reinterpret_cast<uint32_t*>(&h);
}
__device__ __forceinline__ float2 unpack_bf16(uint32_t u) {
    return __bfloat1622float2(*reinterpret_cast<__nv_bfloat162*>(&u));
}

// ---------------- prep: zero scratch + partial sums of edge_attr ----------------
__global__ void prep_kernel(const float* __restrict__ ea) {
    __shared__ float sh[8];
    int i = blockIdx.x * blockDim.x + threadIdx.x;
    if (i < NN) g_cur[i] = 0;
    if (i < GG * HIDD) g_sums[i] = 0.f;
    if (i < GG) g_cnt[i] = 0.f;
    if (i < 8)  g_scal[i] = 0.f;
    float s = 0.f;
    for (size_t e = i; e < EE; e += (size_t)512 * 256) s += ea[e];
    for (int o = 16; o; o >>= 1) s += __shfl_xor_sync(0xffffffffu, s, o);
    if ((threadIdx.x & 31) == 0) sh[threadIdx.x >> 5] = s;
    __syncthreads();
    if (threadIdx.x < 8) {
        float v = sh[threadIdx.x];
        for (int o = 4; o; o >>= 1) v += __shfl_xor_sync(0xffu, v, o);
        if (threadIdx.x == 0) g_part[blockIdx.x] = v;
    }
}

// ---------------- CSR build: histogram of dst ----------------
__global__ void hist_kernel(const int* __restrict__ ei) {
    int e = blockIdx.x * blockDim.x + threadIdx.x;
    if (e >= ELOOP) return;
    int d = (e < EE) ? ei[EE + e] : (e - EE);
    atomicAdd(&g_cur[d], 1);
}

// ------- scan (single block, 1024 thr): finalize mean + ce dots + exclusive scan -------
#define CHUNK 49   // 1024*49 = 50176 >= NN
__global__ void scan_kernel(const float* __restrict__ We1, const float* __restrict__ ae1,
                            const float* __restrict__ We2, const float* __restrict__ ae2) {
    __shared__ int ps[1024];
    __shared__ float fs[32];
    int t = threadIdx.x;
    int lane = t & 31, warp = t >> 5;
    float v = (t < 512) ? g_part[t] : 0.f;
    for (int o = 16; o; o >>= 1) v += __shfl_xor_sync(0xffffffffu, v, o);
    if (lane == 0) fs[warp] = v;
    __syncthreads();
    if (t < 32) {
        float u = fs[t];
        for (int o = 16; o; o >>= 1) u += __shfl_xor_sync(0xffffffffu, u, o);
        if (t == 0) g_scal[0] = u;
    }
    if (t < C1) atomicAdd(&g_scal[1 + (t >> 6)], We1[t] * ae1[t]);
    if (t < 64) atomicAdd(&g_scal[5], We2[t] * ae2[t]);
    int base = t * CHUNK;
    int s = 0;
    for (int i = 0; i < CHUNK; i++) {
        int idx = base + i;
        if (idx < NN) s += g_cur[idx];
    }
    ps[t] = s;
    __syncthreads();
    for (int off = 1; off < 1024; off <<= 1) {
        int w = (t >= off) ? ps[t - off] : 0;
        __syncthreads();
        ps[t] += w;
        __syncthreads();
    }
    int run = ps[t] - s;
    for (int i = 0; i < CHUNK; i++) {
        int idx = base + i;
        if (idx < NN) {
            int d = g_cur[idx];
            g_row[idx] = run;
            g_cur[idx] = run;
            run += d;
        }
    }
    if (t == 0) g_row[NN] = ELOOP;
}

// ---------------- CSR build: scatter (src, edge_attr) ----------------
__global__ void scatter_kernel(const int* __restrict__ ei, const float* __restrict__ ea) {
    int e = blockIdx.x * blockDim.x + threadIdx.x;
    if (e >= ELOOP) return;
    int s, d; float att;
    if (e < EE) { s = ei[e]; d = ei[EE + e]; att = ea[e]; }
    else        { s = d = e - EE; att = g_scal[0] * (1.0f / EE); }
    int pos = atomicAdd(&g_cur[d], 1);
    g_elist[pos] = make_int2(s, __float_as_int(att));
}

// ---------------- TF32 tensor-core GEMM, double-buffered, dual fp32+bf16 output ----
template<int BN, int K>
__device__ __forceinline__ void gemm_tf32_body(const float* __restrict__ A,
                                               const float* __restrict__ B,
                                               float* __restrict__ C,
                                               uint32_t* __restrict__ Cb,
                                               int M, int Ncol) {
    constexpr int NF = BN / 16;
    __shared__ uint32_t As[2][128][20];
    __shared__ uint32_t Bs[2][16][BN + 8];
    int tid = threadIdx.x;
    int warp = tid >> 5, lane = tid & 31;
    int warp_m = warp & 3;
    int warp_n = warp >> 2;
    int m0 = blockIdx.y * 128, n0 = blockIdx.x * BN;
    int g = lane >> 2, t4 = lane & 3;

    int arow = tid >> 1, acb = (tid & 1) * 8;
    int brow = tid >> 4;
    int bcb  = (BN == 128) ? (tid & 15) * 8 : (tid & 15) * 4;

    float acc[2][NF][4];
#pragma unroll
    for (int mf = 0; mf < 2; mf++)
#pragma unroll
        for (int nf = 0; nf < NF; nf++)
#pragma unroll
            for (int i = 0; i < 4; i++) acc[mf][nf][i] = 0.f;

    float4 pa0, pa1, pb0, pb1;
    auto load_tile = [&](int k0) {
        pa0 = make_float4(0.f, 0.f, 0.f, 0.f);
        pa1 = make_float4(0.f, 0.f, 0.f, 0.f);
        if (m0 + arow < M) {
            const float* p = A + (size_t)(m0 + arow) * K + k0 + acb;
            pa0 = *(const float4*)p;
            pa1 = *(const float4*)(p + 4);
        }
        const float* q = B + (size_t)(k0 + brow) * Ncol + n0 + bcb;
        pb0 = *(const float4*)q;
        if (BN == 128) pb1 = *(const float4*)(q + 4);
    };
    auto store_tile = [&](int buf) {
        *(uint4*)&As[buf][arow][acb]     = *reinterpret_cast<uint4*>(&pa0);
        *(uint4*)&As[buf][arow][acb + 4] = *reinterpret_cast<uint4*>(&pa1);
        *(uint4*)&Bs[buf][brow][bcb]     = *reinterpret_cast<uint4*>(&pb0);
        if (BN == 128)
            *(uint4*)&Bs[buf][brow][bcb + 4] = *reinterpret_cast<uint4*>(&pb1);
    };
    auto compute = [&](int buf) {
#pragma unroll
        for (int ks = 0; ks < 16; ks += 8) {
            uint32_t a[2][4];
#pragma unroll
            for (int mf = 0; mf < 2; mf++) {
                int rb = warp_m * 32 + mf * 16;
                a[mf][0] = As[buf][rb + g][ks + t4];
                a[mf][1] = As[buf][rb + 8 + g][ks + t4];
                a[mf][2] = As[buf][rb + g][ks + 4 + t4];
                a[mf][3] = As[buf][rb + 8 + g][ks + 4 + t4];
            }
#pragma unroll
            for (int nf = 0; nf < NF; nf++) {
                int cb = warp_n * (BN / 2) + nf * 8;
                uint32_t b0 = Bs[buf][ks + t4][cb + g];
                uint32_t b1 = Bs[buf][ks + 4 + t4][cb + g];
#pragma unroll
                for (int mf = 0; mf < 2; mf++) {
                    asm volatile(
                        "mma.sync.aligned.m16n8k8.row.col.f32.tf32.tf32.f32 "
                        "{%0,%1,%2,%3}, {%4,%5,%6,%7}, {%8,%9}, {%0,%1,%2,%3};"
                        : "+f"(acc[mf][nf][0]), "+f"(acc[mf][nf][1]),
                          "+f"(acc[mf][nf][2]), "+f"(acc[mf][nf][3])
                        : "r"(a[mf][0]), "r"(a[mf][1]), "r"(a[mf][2]), "r"(a[mf][3]),
                          "r"(b0), "r"(b1));
                }
            }
        }
    };

    load_tile(0);
    store_tile(0);
    __syncthreads();
    int cur = 0;
    for (int k0 = 0; k0 < K; k0 += 16) {
        bool more = (k0 + 16 < K);
        if (more) load_tile(k0 + 16);
        compute(cur);
        if (more) store_tile(cur ^ 1);
        __syncthreads();
        cur ^= 1;
    }

#pragma unroll
    for (int mf = 0; mf < 2; mf++) {
#pragma unroll
        for (int nf = 0; nf < NF; nf++) {
            int row0 = m0 + warp_m * 32 + mf * 16 + g;
            int col  = n0 + warp_n * (BN / 2) + nf * 8 + 2 * t4;
            if (row0 < M) {
                *(float2*)(C + (size_t)row0 * Ncol + col) =
                    make_float2(acc[mf][nf][0], acc[mf][nf][1]);
                Cb[(size_t)row0 * (Ncol / 2) + col / 2] = pack_bf16(acc[mf][nf][0], acc[mf][nf][1]);
            }
            if (row0 + 8 < M) {
                *(float2*)(C + (size_t)(row0 + 8) * Ncol + col) =
                    make_float2(acc[mf][nf][2], acc[mf][nf][3]);
                Cb[(size_t)(row0 + 8) * (Ncol / 2) + col / 2] = pack_bf16(acc[mf][nf][2], acc[mf][nf][3]);
            }
        }
    }
}

__global__ void gemm1_kernel(const float* __restrict__ x, const float* __restrict__ W1) {
    gemm_tf32_body<128, FIN>(x, W1, g_h1, g_h1b, NN, C1);
}
__global__ void gemm2_kernel(const float* __restrict__ W2) {
    gemm_tf32_body<64, C1>(g_out1, W2, g_h2, g_h2b, NN, HIDD);
}

// ---------------- per-node attention logits, layer 1 (warp per node) ----------------
__global__ void logits1_kernel(const float* __restrict__ as1, const float* __restrict__ ad1) {
    int w = (blockIdx.x * blockDim.x + threadIdx.x) >> 5;
    int lane = threadIdx.x & 31;
    if (w >= NN) return;
    const float4* hp = (const float4*)(g_h1 + (size_t)w * C1);
    const float4* sp = (const float4*)as1;
    const float4* dp = (const float4*)ad1;
    float4 h0 = hp[lane * 2], h1v = hp[lane * 2 + 1];
    float4 s0 = sp[lane * 2], s1  = sp[lane * 2 + 1];
    float4 d0 = dp[lane * 2], d1  = dp[lane * 2 + 1];
    float ss = h0.x*s0.x + h0.y*s0.y + h0.z*s0.z + h0.w*s0.w
             + h1v.x*s1.x + h1v.y*s1.y + h1v.z*s1.z + h1v.w*s1.w;
    float dd = h0.x*d0.x + h0.y*d0.y + h0.z*d0.z + h0.w*d0.w
             + h1v.x*d1.x + h1v.y*d1.y + h1v.z*d1.z + h1v.w*d1.w;
    for (int o = 4; o; o >>= 1) {
        ss += __shfl_down_sync(0xffffffffu, ss, o, 8);
        dd += __shfl_down_sync(0xffffffffu, dd, o, 8);
    }
    if ((lane & 7) == 0) {
        g_als1[w * 4 + (lane >> 3)] = ss;
        g_ald1[w * 4 + (lane >> 3)] = dd;
    }
}

// ---- layer-1 aggregation: warp per dst node, bf16 gather, fp32 accumulate ----
__global__ void agg1_kernel(const float* __restrict__ b1) {
    int n = (blockIdx.x * blockDim.x + threadIdx.x) >> 5;
    int lane = threadIdx.x & 31;
    if (n >= NN) return;
    int beg = g_row[n], end = g_row[n + 1];
    int h = lane >> 3;
    float ald = g_ald1[n * 4 + h];
    float ce  = g_scal[1 + h];
    float4 acc0 = make_float4(0.f, 0.f, 0.f, 0.f);
    float4 acc1 = make_float4(0.f, 0.f, 0.f, 0.f);
    float den = 0.f;
    int j = beg;
    for (; j + 4 <= end; j += 4) {
        int2 se[4];
#pragma unroll
        for (int q = 0; q < 4; q++) se[q] = g_elist[j + q];
        float ex[4];
        uint4 p[4];
#pragma unroll
        for (int q = 0; q < 4; q++) {
            p[q] = ((const uint4*)(g_h1b + (size_t)se[q].x * (C1 / 2)))[lane];
            float z = g_als1[se[q].x * 4 + h] + ald + __int_as_float(se[q].y) * ce;
            z = z > 0.f ? z : 0.2f * z;
            ex[q] = expf(z);
        }
#pragma unroll
        for (int q = 0; q < 4; q++) {
            float2 f0 = unpack_bf16(p[q].x), f1 = unpack_bf16(p[q].y);
            float2 f2 = unpack_bf16(p[q].z), f3 = unpack_bf16(p[q].w);
            den += ex[q];
            acc0.x += ex[q] * f0.x; acc0.y += ex[q] * f0.y;
            acc0.z += ex[q] * f1.x; acc0.w += ex[q] * f1.y;
            acc1.x += ex[q] * f2.x; acc1.y += ex[q] * f2.y;
            acc1.z += ex[q] * f3.x; acc1.w += ex[q] * f3.y;
        }
    }
    for (; j < end; j++) {
        int2 se = g_elist[j];
        uint4 p = ((const uint4*)(g_h1b + (size_t)se.x * (C1 / 2)))[lane];
        float z = g_als1[se.x * 4 + h] + ald + __int_as_float(se.y) * ce;
        z = z > 0.f ? z : 0.2f * z;
        float ex = expf(z);
        float2 f0 = unpack_bf16(p.x), f1 = unpack_bf16(p.y);
        float2 f2 = unpack_bf16(p.z), f3 = unpack_bf16(p.w);
        den += ex;
        acc0.x += ex * f0.x; acc0.y += ex * f0.y;
        acc0.z += ex * f1.x; acc0.w += ex * f1.y;
        acc1.x += ex * f2.x; acc1.y += ex * f2.y;
        acc1.z += ex * f3.x; acc1.w += ex * f3.y;
    }
    float inv = 1.f / (den + 1e-16f);
    const float4* bp = (const float4*)b1;
    float4 bb0 = bp[lane * 2], bb1 = bp[lane * 2 + 1];
    float4 o0, o1;
    o0.x = fmaxf(acc0.x * inv + bb0.x, 0.f);
    o0.y = fmaxf(acc0.y * inv + bb0.y, 0.f);
    o0.z = fmaxf(acc0.z * inv + bb0.z, 0.f);
    o0.w = fmaxf(acc0.w * inv + bb0.w, 0.f);
    o1.x = fmaxf(acc1.x * inv + bb1.x, 0.f);
    o1.y = fmaxf(acc1.y * inv + bb1.y, 0.f);
    o1.z = fmaxf(acc1.z * inv + bb1.z, 0.f);
    o1.w = fmaxf(acc1.w * inv + bb1.w, 0.f);
    float4* op = (float4*)(g_out1 + (size_t)n * C1);
    op[lane * 2] = o0;
    op[lane * 2 + 1] = o1;
}

// ---------------- per-node logits, layer 2 (warp per node) ----------------
__global__ void logits2_kernel(const float* __restrict__ as2, const float* __restrict__ ad2) {
    int w = (blockIdx.x * blockDim.x + threadIdx.x) >> 5;
    int lane = threadIdx.x & 31;
    if (w >= NN) return;
    float2 v = ((const float2*)(g_h2 + (size_t)w * HIDD))[lane];
    float2 s = ((const float2*)as2)[lane];
    float2 dv = ((const float2*)ad2)[lane];
    float ss = v.x * s.x + v.y * s.y;
    float dd = v.x * dv.x + v.y * dv.y;
    for (int o = 16; o; o >>= 1) {
        ss += __shfl_xor_sync(0xffffffffu, ss, o);
        dd += __shfl_xor_sync(0xffffffffu, dd, o);
    }
    if (lane == 0) { g_als2[w] = ss; g_ald2[w] = dd; }
}

// ---- layer-2 aggregation (bf16 gather) + bias + LayerNorm + pool ----
__global__ void agg2_ln_pool_kernel(const float* __restrict__ b2,
                                    const float* __restrict__ lng,
                                    const float* __restrict__ lnb,
                                    const int* __restrict__ batch) {
    int n = (blockIdx.x * blockDim.x + threadIdx.x) >> 5;
    int lane = threadIdx.x & 31;
    if (n >= NN) return;
    int beg = g_row[n], end = g_row[n + 1];
    float ald = g_ald2[n];
    float ce  = g_scal[5];
    float2 acc = make_float2(0.f, 0.f);
    float den = 0.f;
    int j = beg;
    for (; j + 4 <= end; j += 4) {
        int2 se[4];
#pragma unroll
        for (int q = 0; q < 4; q++) se[q] = g_elist[j + q];
        float ex[4];
        uint32_t p[4];
#pragma unroll
        for (int q = 0; q < 4; q++) {
            p[q] = (g_h2b + (size_t)se[q].x * (HIDD / 2))[lane];
            float z = g_als2[se[q].x] + ald + __int_as_float(se[q].y) * ce;
            z = z > 0.f ? z : 0.2f * z;
            ex[q] = expf(z);
        }
#pragma unroll
        for (int q = 0; q < 4; q++) {
            float2 f = unpack_bf16(p[q]);
            den += ex[q];
            acc.x += ex[q] * f.x;
            acc.y += ex[q] * f.y;
        }
    }
    for (; j < end; j++) {
        int2 se = g_elist[j];
        uint32_t p = (g_h2b + (size_t)se.x * (HIDD / 2))[lane];
        float z = g_als2[se.x] + ald + __int_as_float(se.y) * ce;
        z = z > 0.f ? z : 0.2f * z;
        float ex = expf(z);
        float2 f = unpack_bf16(p);
        den += ex;
        acc.x += ex * f.x;
        acc.y += ex * f.y;
    }
    float inv = 1.f / (den + 1e-16f);
    float2 bb = ((const float2*)b2)[lane];
    float vx = acc.x * inv + bb.x;
    float vy = acc.y * inv + bb.y;
    float s = vx + vy;
    for (int o = 16; o; o >>= 1) s += __shfl_xor_sync(0xffffffffu, s, o);
    float mu = s * (1.0f / 64.0f);
    float dx = vx - mu, dy = vy - mu;
    float q = dx * dx + dy * dy;
    for (int o = 16; o; o >>= 1) q += __shfl_xor_sync(0xffffffffu, q, o);
    float r = rsqrtf(q * (1.0f / 64.0f) + 1e-5f);
    float y0 = dx * r * lng[lane * 2]     + lnb[lane * 2];
    float y1 = dy * r * lng[lane * 2 + 1] + lnb[lane * 2 + 1];
    int g = batch[n];
    atomicAdd(&g_sums[g * 64 + lane * 2],     y0);
    atomicAdd(&g_sums[g * 64 + lane * 2 + 1], y1);
    if (lane == 0) atomicAdd(&g_cnt[g], 1.0f);
}

// ---------------- per-graph MLP head (block per graph, 64 threads) ----------------
__global__ void mlp_kernel(const float* __restrict__ clin, const float* __restrict__ met,
                           const float* __restrict__ Wf1, const float* __restrict__ bf1,
                           const float* __restrict__ Wf2, const float* __restrict__ bf2,
                           const float* __restrict__ Wr,  const float* __restrict__ br,
                           float* __restrict__ out) {
    int g = blockIdx.x, t = threadIdx.x;   // 64 threads
    __shared__ float fused[FUSED_IN];
    __shared__ float l1[64];
    __shared__ float l2[32];
    float cnt = g_cnt[g]; cnt = cnt > 1.f ? cnt : 1.f;
    float e = g_sums[g * 64 + t] / cnt;
    fused[t] = e;
    out[GG + g * 64 + t] = e;              // graph_embedding at offset 64
    if (t < 32) fused[64 + t] = clin[g * 32 + t];
    fused[96 + t]  = met[g * 128 + t];
    fused[160 + t] = met[g * 128 + 64 + t];
    __syncthreads();
    float acc = bf1[t];
#pragma unroll 8
    for (int k = 0; k < FUSED_IN; k++) acc += fused[k] * Wf1[k * 64 + t];
    l1[t] = acc > 0.f ? acc : 0.f;
    __syncthreads();
    if (t < 32) {
        float a2 = bf2[t];
#pragma unroll 8
        for (int j = 0; j < 64; j++) a2 += l1[j] * Wf2[j * 32 + t];
        a2 = a2 > 0.f ? a2 : 0.f;
        l2[t] = a2;
        out[GG + GG * 64 + g * 32 + t] = a2;   // latent at offset 64 + 4096
    }
    __syncthreads();
    if (t == 0) {
        float r = br[0];
#pragma unroll
        for (int j = 0; j < 32; j++) r += l2[j] * Wr[j];
        out[g] = r;                        // risk at offset 0
    }
}

// ---------------- launch ----------------
extern "C" void kernel_launch(void* const* d_in, const int* in_sizes, int n_in,
                              void* d_out, int out_size) {
    const float* x    = (const float*)d_in[0];
    const int*   ei   = (const int*)d_in[1];
    const float* ea   = (const float*)d_in[2];
    const int*   bat  = (const int*)d_in[3];
    const float* clin = (const float*)d_in[4];
    const float* met  = (const float*)d_in[5];
    const float* W1   = (const float*)d_in[6];
    const float* as1  = (const float*)d_in[7];
    const float* ad1  = (const float*)d_in[8];
    const float* ae1  = (const float*)d_in[9];
    const float* We1  = (const float*)d_in[10];
    const float* b1   = (const float*)d_in[11];
    const float* W2   = (const float*)d_in[12];
    const float* as2  = (const float*)d_in[13];
    const float* ad2  = (const float*)d_in[14];
    const float* ae2  = (const float*)d_in[15];
    const float* We2  = (const float*)d_in[16];
    const float* b2   = (const float*)d_in[17];
    const float* lng  = (const float*)d_in[18];
    const float* lnb  = (const float*)d_in[19];
    const float* Wf1  = (const float*)d_in[20];
    const float* bf1  = (const float*)d_in[21];
    const float* Wf2  = (const float*)d_in[22];
    const float* bf2  = (const float*)d_in[23];
    const float* Wr   = (const float*)d_in[24];
    const float* br   = (const float*)d_in[25];
    float* out = (float*)d_out;

    // fork: CSR chain on side stream, GEMM/logits on main stream
    cudaStream_t s2;
    cudaEvent_t e0, e1;
    cudaStreamCreateWithFlags(&s2, cudaStreamNonBlocking);
    cudaEventCreateWithFlags(&e0, cudaEventDisableTiming);
    cudaEventCreateWithFlags(&e1, cudaEventDisableTiming);

    cudaEventRecord(e0, 0);
    cudaStreamWaitEvent(s2, e0, 0);

    prep_kernel<<<512, 256, 0, s2>>>(ea);                       // 0
    hist_kernel<<<(ELOOP + 255) / 256, 256, 0, s2>>>(ei);       // 1
    gemm1_kernel<<<dim3(C1 / 128, (NN + 127) / 128), 256>>>(x, W1);       // 2
    logits1_kernel<<<(NN * 32 + 255) / 256, 256>>>(as1, ad1);   // 3 (profiled slot)
    scan_kernel<<<1, 1024, 0, s2>>>(We1, ae1, We2, ae2);        // 4
    scatter_kernel<<<(ELOOP + 255) / 256, 256, 0, s2>>>(ei, ea);// 5
    cudaEventRecord(e1, s2);
    cudaStreamWaitEvent(0, e1, 0);

    // layer 1 aggregation (needs CSR + logits)
    agg1_kernel<<<(NN * 32 + 255) / 256, 256>>>(b1);

    // layer 2
    gemm2_kernel<<<dim3(1, (NN + 127) / 128), 256>>>(W2);
    logits2_kernel<<<(NN * 32 + 255) / 256, 256>>>(as2, ad2);
    agg2_ln_pool_kernel<<<(NN * 32 + 255) / 256, 256>>>(b2, lng, lnb, bat);

    // head
    mlp_kernel<<<GG, 64>>>(clin, met, Wf1, bf1, Wf2, bf2, Wr, br, out);
    // streams/events intentionally not destroyed (graph may reference them;
    // kernel_launch is called only a handful of times per process)
}

// round 9
// speedup vs baseline: 4.5970x; 1.0014x over previous
#include <cuda_runtime.h>
#include <cuda_bf16.h>
#include <cstdint>

// ---------------- fixed problem shapes ----------------
#define NN      50000
#define EE      800000
#define ELOOP   850000        // EE + NN self loops
#define GG      64
#define FIN     128
#define HIDD    64
#define HEADS   4
#define C1      256           // HEADS*HIDD
#define CLIN    32
#define MET     128
#define FUSED_IN 224          // HID + CLIN + MET

// ---------------- device scratch (no allocs allowed) ----------------
__device__ uint32_t g_h1b [(size_t)NN * (C1/2)];  // bf16x2 packed h1 (agg gather)
__device__ float    g_out1[(size_t)NN * C1];      // layer1 output (post bias+relu)
__device__ uint32_t g_h2b [(size_t)NN * (HIDD/2)];// bf16x2 packed h2
__device__ float g_als1[NN * HEADS];
__device__ float g_ald1[NN * HEADS];
__device__ float g_als2[NN];
__device__ float g_ald2[NN];
__device__ float g_sums[GG * HIDD];
__device__ float g_cnt [GG];
__device__ float g_scal[8];     // [0]=sum(edge_attr), [1..4]=ce1[h], [5]=ce2
__device__ float g_part[512];   // per-block partial sums of edge_attr
// CSR by destination
__device__ int  g_row [NN + 1];
__device__ int  g_cur [NN];     // hist -> cursor
__device__ int2 g_elist[ELOOP]; // (src, float_bits(edge_attr)) sorted by dst

__device__ __forceinline__ uint32_t pack_bf16(float a, float b) {
    __nv_bfloat162 h = __float22bfloat162_rn(make_float2(a, b));
    return *reinterpret_cast<uint32_t*>(&h);
}
__device__ __forceinline__ float2 unpack_bf16(uint32_t u) {
    return __bfloat1622float2(*reinterpret_cast<__nv_bfloat162*>(&u));
}

// ---------------- prep: zero scratch + partial sums of edge_attr ----------------
__global__ void prep_kernel(const float* __restrict__ ea) {
    __shared__ float sh[8];
    int i = blockIdx.x * blockDim.x + threadIdx.x;
    if (i < NN) { g_cur[i] = 0; g_als2[i] = 0.f; g_ald2[i] = 0.f; }
    if (i < GG * HIDD) g_sums[i] = 0.f;
    if (i < GG) g_cnt[i] = 0.f;
    if (i < 8)  g_scal[i] = 0.f;
    float s = 0.f;
    for (size_t e = i; e < EE; e += (size_t)512 * 256) s += ea[e];
    for (int o = 16; o; o >>= 1) s += __shfl_xor_sync(0xffffffffu, s, o);
    if ((threadIdx.x & 31) == 0) sh[threadIdx.x >> 5] = s;
    __syncthreads();
    if (threadIdx.x < 8) {
        float v = sh[threadIdx.x];
        for (int o = 4; o; o >>= 1) v += __shfl_xor_sync(0xffu, v, o);
        if (threadIdx.x == 0) g_part[blockIdx.x] = v;
    }
}

// ---------------- CSR build: histogram of dst ----------------
__global__ void hist_kernel(const int* __restrict__ ei) {
    int e = blockIdx.x * blockDim.x + threadIdx.x;
    if (e >= ELOOP) return;
    int d = (e < EE) ? ei[EE + e] : (e - EE);
    atomicAdd(&g_cur[d], 1);
}

// ------- scan (single block, 1024 thr): finalize mean + ce dots + exclusive scan -------
#define CHUNK 49   // 1024*49 = 50176 >= NN
__global__ void scan_kernel(const float* __restrict__ We1, const float* __restrict__ ae1,
                            const float* __restrict__ We2, const float* __restrict__ ae2) {
    __shared__ int ps[1024];
    __shared__ float fs[32];
    int t = threadIdx.x;
    int lane = t & 31, warp = t >> 5;
    float v = (t < 512) ? g_part[t] : 0.f;
    for (int o = 16; o; o >>= 1) v += __shfl_xor_sync(0xffffffffu, v, o);
    if (lane == 0) fs[warp] = v;
    __syncthreads();
    if (t < 32) {
        float u = fs[t];
        for (int o = 16; o; o >>= 1) u += __shfl_xor_sync(0xffffffffu, u, o);
        if (t == 0) g_scal[0] = u;
    }
    if (t < C1) atomicAdd(&g_scal[1 + (t >> 6)], We1[t] * ae1[t]);
    if (t < 64) atomicAdd(&g_scal[5], We2[t] * ae2[t]);
    int base = t * CHUNK;
    int s = 0;
    for (int i = 0; i < CHUNK; i++) {
        int idx = base + i;
        if (idx < NN) s += g_cur[idx];
    }
    ps[t] = s;
    __syncthreads();
    for (int off = 1; off < 1024; off <<= 1) {
        int w = (t >= off) ? ps[t - off] : 0;
        __syncthreads();
        ps[t] += w;
        __syncthreads();
    }
    int run = ps[t] - s;
    for (int i = 0; i < CHUNK; i++) {
        int idx = base + i;
        if (idx < NN) {
            int d = g_cur[idx];
            g_row[idx] = run;
            g_cur[idx] = run;
            run += d;
        }
    }
    if (t == 0) g_row[NN] = ELOOP;
}

// ---------------- CSR build: scatter (src, edge_attr) ----------------
__global__ void scatter_kernel(const int* __restrict__ ei, const float* __restrict__ ea) {
    int e = blockIdx.x * blockDim.x + threadIdx.x;
    if (e >= ELOOP) return;
    int s, d; float att;
    if (e < EE) { s = ei[e]; d = ei[EE + e]; att = ea[e]; }
    else        { s = d = e - EE; att = g_scal[0] * (1.0f / EE); }
    int pos = atomicAdd(&g_cur[d], 1);
    g_elist[pos] = make_int2(s, __float_as_int(att));
}

// ---- TF32 GEMM, double-buffered, bf16 output + FUSED attention logits ----
// LAYER=1: per-warp tile is one full head (64 cols) -> direct logit store.
// LAYER=2: warp holds 32 of 64 cols -> atomicAdd partial logits.
template<int BN, int K, int LAYER>
__device__ __forceinline__ void gemm_tf32_body(const float* __restrict__ A,
                                               const float* __restrict__ B,
                                               uint32_t* __restrict__ Cb,
                                               const float* __restrict__ avS,
                                               const float* __restrict__ avD,
                                               int M, int Ncol) {
    constexpr int NF = BN / 16;
    __shared__ uint32_t As[2][128][20];
    __shared__ uint32_t Bs[2][16][BN + 8];
    int tid = threadIdx.x;
    int warp = tid >> 5, lane = tid & 31;
    int warp_m = warp & 3;
    int warp_n = warp >> 2;
    int m0 = blockIdx.y * 128, n0 = blockIdx.x * BN;
    int g = lane >> 2, t4 = lane & 3;

    int arow = tid >> 1, acb = (tid & 1) * 8;
    int brow = tid >> 4;
    int bcb  = (BN == 128) ? (tid & 15) * 8 : (tid & 15) * 4;

    float acc[2][NF][4];
#pragma unroll
    for (int mf = 0; mf < 2; mf++)
#pragma unroll
        for (int nf = 0; nf < NF; nf++)
#pragma unroll
            for (int i = 0; i < 4; i++) acc[mf][nf][i] = 0.f;

    float4 pa0, pa1, pb0, pb1;
    auto load_tile = [&](int k0) {
        pa0 = make_float4(0.f, 0.f, 0.f, 0.f);
        pa1 = make_float4(0.f, 0.f, 0.f, 0.f);
        if (m0 + arow < M) {
            const float* p = A + (size_t)(m0 + arow) * K + k0 + acb;
            pa0 = *(const float4*)p;
            pa1 = *(const float4*)(p + 4);
        }
        const float* q = B + (size_t)(k0 + brow) * Ncol + n0 + bcb;
        pb0 = *(const float4*)q;
        if (BN == 128) pb1 = *(const float4*)(q + 4);
    };
    auto store_tile = [&](int buf) {
        *(uint4*)&As[buf][arow][acb]     = *reinterpret_cast<uint4*>(&pa0);
        *(uint4*)&As[buf][arow][acb + 4] = *reinterpret_cast<uint4*>(&pa1);
        *(uint4*)&Bs[buf][brow][bcb]     = *reinterpret_cast<uint4*>(&pb0);
        if (BN == 128)
            *(uint4*)&Bs[buf][brow][bcb + 4] = *reinterpret_cast<uint4*>(&pb1);
    };
    auto compute = [&](int buf) {
#pragma unroll
        for (int ks = 0; ks < 16; ks += 8) {
            uint32_t a[2][4];
#pragma unroll
            for (int mf = 0; mf < 2; mf++) {
                int rb = warp_m * 32 + mf * 16;
                a[mf][0] = As[buf][rb + g][ks + t4];
                a[mf][1] = As[buf][rb + 8 + g][ks + t4];
                a[mf][2] = As[buf][rb + g][ks + 4 + t4];
                a[mf][3] = As[buf][rb + 8 + g][ks + 4 + t4];
            }
#pragma unroll
            for (int nf = 0; nf < NF; nf++) {
                int cb = warp_n * (BN / 2) + nf * 8;
                uint32_t b0 = Bs[buf][ks + t4][cb + g];
                uint32_t b1 = Bs[buf][ks + 4 + t4][cb + g];
#pragma unroll
                for (int mf = 0; mf < 2; mf++) {
                    asm volatile(
                        "mma.sync.aligned.m16n8k8.row.col.f32.tf32.tf32.f32 "
                        "{%0,%1,%2,%3}, {%4,%5,%6,%7}, {%8,%9}, {%0,%1,%2,%3};"
                        : "+f"(acc[mf][nf][0]), "+f"(acc[mf][nf][1]),
                          "+f"(acc[mf][nf][2]), "+f"(acc[mf][nf][3])
                        : "r"(a[mf][0]), "r"(a[mf][1]), "r"(a[mf][2]), "r"(a[mf][3]),
                          "r"(b0), "r"(b1));
                }
            }
        }
    };

    load_tile(0);
    store_tile(0);
    __syncthreads();
    int cur = 0;
    for (int k0 = 0; k0 < K; k0 += 16) {
        bool more = (k0 + 16 < K);
        if (more) load_tile(k0 + 16);
        compute(cur);
        if (more) store_tile(cur ^ 1);
        __syncthreads();
        cur ^= 1;
    }

    // ---- bf16 store ----
#pragma unroll
    for (int mf = 0; mf < 2; mf++) {
#pragma unroll
        for (int nf = 0; nf < NF; nf++) {
            int row0 = m0 + warp_m * 32 + mf * 16 + g;
            int col  = n0 + warp_n * (BN / 2) + nf * 8 + 2 * t4;
            if (row0 < M)
                Cb[(size_t)row0 * (Ncol / 2) + col / 2] = pack_bf16(acc[mf][nf][0], acc[mf][nf][1]);
            if (row0 + 8 < M)
                Cb[(size_t)(row0 + 8) * (Ncol / 2) + col / 2] = pack_bf16(acc[mf][nf][2], acc[mf][nf][3]);
        }
    }

    // ---- fused attention logits ----
    // this thread's columns within the logit vector: (warp_n*(BN/2)) + nf*8 + 2*t4 (+1)
    float2 wS[NF], wD[NF];
    int cbase = (LAYER == 1) ? ((blockIdx.x * 2 + warp_n) * 64) : (warp_n * (BN / 2));
#pragma unroll
    for (int nf = 0; nf < NF; nf++) {
        int c = (LAYER == 1) ? (cbase + nf * 8 + 2 * t4) : (cbase + nf * 8 + 2 * t4);
        wS[nf] = *(const float2*)(avS + c);
        wD[nf] = *(const float2*)(avD + c);
    }
#pragma unroll
    for (int mf = 0; mf < 2; mf++) {
        float ss0 = 0.f, dd0 = 0.f, ss1 = 0.f, dd1 = 0.f;
#pragma unroll
        for (int nf = 0; nf < NF; nf++) {
            ss0 += acc[mf][nf][0] * wS[nf].x + acc[mf][nf][1] * wS[nf].y;
            dd0 += acc[mf][nf][0] * wD[nf].x + acc[mf][nf][1] * wD[nf].y;
            ss1 += acc[mf][nf][2] * wS[nf].x + acc[mf][nf][3] * wS[nf].y;
            dd1 += acc[mf][nf][2] * wD[nf].x + acc[mf][nf][3] * wD[nf].y;
        }
        // reduce across the 4 t4-threads (lanes g*4 + t4)
        ss0 += __shfl_xor_sync(0xffffffffu, ss0, 1); ss0 += __shfl_xor_sync(0xffffffffu, ss0, 2);
        dd0 += __shfl_xor_sync(0xffffffffu, dd0, 1); dd0 += __shfl_xor_sync(0xffffffffu, dd0, 2);
        ss1 += __shfl_xor_sync(0xffffffffu, ss1, 1); ss1 += __shfl_xor_sync(0xffffffffu, ss1, 2);
        dd1 += __shfl_xor_sync(0xffffffffu, dd1, 1); dd1 += __shfl_xor_sync(0xffffffffu, dd1, 2);
        if (t4 == 0) {
            int row0 = m0 + warp_m * 32 + mf * 16 + g;
            if (LAYER == 1) {
                int head = blockIdx.x * 2 + warp_n;
                if (row0 < M)     { g_als1[row0 * 4 + head] = ss0; g_ald1[row0 * 4 + head] = dd0; }
                if (row0 + 8 < M) { g_als1[(row0 + 8) * 4 + head] = ss1; g_ald1[(row0 + 8) * 4 + head] = dd1; }
            } else {
                if (row0 < M)     { atomicAdd(&g_als2[row0], ss0); atomicAdd(&g_ald2[row0], dd0); }
                if (row0 + 8 < M) { atomicAdd(&g_als2[row0 + 8], ss1); atomicAdd(&g_ald2[row0 + 8], dd1); }
            }
        }
    }
}

__global__ void __launch_bounds__(256, 2)
gemm1_kernel(const float* __restrict__ x, const float* __restrict__ W1,
             const float* __restrict__ as1, const float* __restrict__ ad1) {
    gemm_tf32_body<128, FIN, 1>(x, W1, g_h1b, as1, ad1, NN, C1);
}
__global__ void __launch_bounds__(256, 2)
gemm2_kernel(const float* __restrict__ W2,
             const float* __restrict__ as2, const float* __restrict__ ad2) {
    gemm_tf32_body<64, C1, 2>(g_out1, W2, g_h2b, as2, ad2, NN, HIDD);
}

// ---- layer-1 aggregation: warp per dst node, bf16 gather, fp32 accumulate ----
__global__ void agg1_kernel(const float* __restrict__ b1) {
    int n = (blockIdx.x * blockDim.x + threadIdx.x) >> 5;
    int lane = threadIdx.x & 31;
    if (n >= NN) return;
    int beg = g_row[n], end = g_row[n + 1];
    int h = lane >> 3;
    float ald = g_ald1[n * 4 + h];
    float ce  = g_scal[1 + h];
    float4 acc0 = make_float4(0.f, 0.f, 0.f, 0.f);
    float4 acc1 = make_float4(0.f, 0.f, 0.f, 0.f);
    float den = 0.f;
    int j = beg;
    for (; j + 4 <= end; j += 4) {
        int2 se[4];
#pragma unroll
        for (int q = 0; q < 4; q++) se[q] = g_elist[j + q];
        float ex[4];
        uint4 p[4];
#pragma unroll
        for (int q = 0; q < 4; q++) {
            p[q] = ((const uint4*)(g_h1b + (size_t)se[q].x * (C1 / 2)))[lane];
            float z = g_als1[se[q].x * 4 + h] + ald + __int_as_float(se[q].y) * ce;
            z = z > 0.f ? z : 0.2f * z;
            ex[q] = expf(z);
        }
#pragma unroll
        for (int q = 0; q < 4; q++) {
            float2 f0 = unpack_bf16(p[q].x), f1 = unpack_bf16(p[q].y);
            float2 f2 = unpack_bf16(p[q].z), f3 = unpack_bf16(p[q].w);
            den += ex[q];
            acc0.x += ex[q] * f0.x; acc0.y += ex[q] * f0.y;
            acc0.z += ex[q] * f1.x; acc0.w += ex[q] * f1.y;
            acc1.x += ex[q] * f2.x; acc1.y += ex[q] * f2.y;
            acc1.z += ex[q] * f3.x; acc1.w += ex[q] * f3.y;
        }
    }
    for (; j < end; j++) {
        int2 se = g_elist[j];
        uint4 p = ((const uint4*)(g_h1b + (size_t)se.x * (C1 / 2)))[lane];
        float z = g_als1[se.x * 4 + h] + ald + __int_as_float(se.y) * ce;
        z = z > 0.f ? z : 0.2f * z;
        float ex = expf(z);
        float2 f0 = unpack_bf16(p.x), f1 = unpack_bf16(p.y);
        float2 f2 = unpack_bf16(p.z), f3 = unpack_bf16(p.w);
        den += ex;
        acc0.x += ex * f0.x; acc0.y += ex * f0.y;
        acc0.z += ex * f1.x; acc0.w += ex * f1.y;
        acc1.x += ex * f2.x; acc1.y += ex * f2.y;
        acc1.z += ex * f3.x; acc1.w += ex * f3.y;
    }
    float inv = 1.f / (den + 1e-16f);
    const float4* bp = (const float4*)b1;
    float4 bb0 = bp[lane * 2], bb1 = bp[lane * 2 + 1];
    float4 o0, o1;
    o0.x = fmaxf(acc0.x * inv + bb0.x, 0.f);
    o0.y = fmaxf(acc0.y * inv + bb0.y, 0.f);
    o0.z = fmaxf(acc0.z * inv + bb0.z, 0.f);
    o0.w = fmaxf(acc0.w * inv + bb0.w, 0.f);
    o1.x = fmaxf(acc1.x * inv + bb1.x, 0.f);
    o1.y = fmaxf(acc1.y * inv + bb1.y, 0.f);
    o1.z = fmaxf(acc1.z * inv + bb1.z, 0.f);
    o1.w = fmaxf(acc1.w * inv + bb1.w, 0.f);
    float4* op = (float4*)(g_out1 + (size_t)n * C1);
    op[lane * 2] = o0;
    op[lane * 2 + 1] = o1;
}

// ---- layer-2 aggregation (bf16 gather) + bias + LayerNorm + pool ----
__global__ void agg2_ln_pool_kernel(const float* __restrict__ b2,
                                    const float* __restrict__ lng,
                                    const float* __restrict__ lnb,
                                    const int* __restrict__ batch) {
    int n = (blockIdx.x * blockDim.x + threadIdx.x) >> 5;
    int lane = threadIdx.x & 31;
    if (n >= NN) return;
    int beg = g_row[n], end = g_row[n + 1];
    float ald = g_ald2[n];
    float ce  = g_scal[5];
    float2 acc = make_float2(0.f, 0.f);
    float den = 0.f;
    int j = beg;
    for (; j + 4 <= end; j += 4) {
        int2 se[4];
#pragma unroll
        for (int q = 0; q < 4; q++) se[q] = g_elist[j + q];
        float ex[4];
        uint32_t p[4];
#pragma unroll
        for (int q = 0; q < 4; q++) {
            p[q] = (g_h2b + (size_t)se[q].x * (HIDD / 2))[lane];
            float z = g_als2[se[q].x] + ald + __int_as_float(se[q].y) * ce;
            z = z > 0.f ? z : 0.2f * z;
            ex[q] = expf(z);
        }
#pragma unroll
        for (int q = 0; q < 4; q++) {
            float2 f = unpack_bf16(p[q]);
            den += ex[q];
            acc.x += ex[q] * f.x;
            acc.y += ex[q] * f.y;
        }
    }
    for (; j < end; j++) {
        int2 se = g_elist[j];
        uint32_t p = (g_h2b + (size_t)se.x * (HIDD / 2))[lane];
        float z = g_als2[se.x] + ald + __int_as_float(se.y) * ce;
        z = z > 0.f ? z : 0.2f * z;
        float ex = expf(z);
        float2 f = unpack_bf16(p);
        den += ex;
        acc.x += ex * f.x;
        acc.y += ex * f.y;
    }
    float inv = 1.f / (den + 1e-16f);
    float2 bb = ((const float2*)b2)[lane];
    float vx = acc.x * inv + bb.x;
    float vy = acc.y * inv + bb.y;
    float s = vx + vy;
    for (int o = 16; o; o >>= 1) s += __shfl_xor_sync(0xffffffffu, s, o);
    float mu = s * (1.0f / 64.0f);
    float dx = vx - mu, dy = vy - mu;
    float q = dx * dx + dy * dy;
    for (int o = 16; o; o >>= 1) q += __shfl_xor_sync(0xffffffffu, q, o);
    float r = rsqrtf(q * (1.0f / 64.0f) + 1e-5f);
    float y0 = dx * r * lng[lane * 2]     + lnb[lane * 2];
    float y1 = dy * r * lng[lane * 2 + 1] + lnb[lane * 2 + 1];
    int g = batch[n];
    atomicAdd(&g_sums[g * 64 + lane * 2],     y0);
    atomicAdd(&g_sums[g * 64 + lane * 2 + 1], y1);
    if (lane == 0) atomicAdd(&g_cnt[g], 1.0f);
}

// ---------------- per-graph MLP head (block per graph, 64 threads) ----------------
__global__ void mlp_kernel(const float* __restrict__ clin, const float* __restrict__ met,
                           const float* __restrict__ Wf1, const float* __restrict__ bf1,
                           const float* __restrict__ Wf2, const float* __restrict__ bf2,
                           const float* __restrict__ Wr,  const float* __restrict__ br,
                           float* __restrict__ out) {
    int g = blockIdx.x, t = threadIdx.x;   // 64 threads
    __shared__ float fused[FUSED_IN];
    __shared__ float l1[64];
    __shared__ float l2[32];
    float cnt = g_cnt[g]; cnt = cnt > 1.f ? cnt : 1.f;
    float e = g_sums[g * 64 + t] / cnt;
    fused[t] = e;
    out[GG + g * 64 + t] = e;              // graph_embedding at offset 64
    if (t < 32) fused[64 + t] = clin[g * 32 + t];
    fused[96 + t]  = met[g * 128 + t];
    fused[160 + t] = met[g * 128 + 64 + t];
    __syncthreads();
    float acc = bf1[t];
#pragma unroll 8
    for (int k = 0; k < FUSED_IN; k++) acc += fused[k] * Wf1[k * 64 + t];
    l1[t] = acc > 0.f ? acc : 0.f;
    __syncthreads();
    if (t < 32) {
        float a2 = bf2[t];
#pragma unroll 8
        for (int j = 0; j < 64; j++) a2 += l1[j] * Wf2[j * 32 + t];
        a2 = a2 > 0.f ? a2 : 0.f;
        l2[t] = a2;
        out[GG + GG * 64 + g * 32 + t] = a2;   // latent at offset 64 + 4096
    }
    __syncthreads();
    if (t == 0) {
        float r = br[0];
#pragma unroll
        for (int j = 0; j < 32; j++) r += l2[j] * Wr[j];
        out[g] = r;                        // risk at offset 0
    }
}

// ---------------- launch ----------------
extern "C" void kernel_launch(void* const* d_in, const int* in_sizes, int n_in,
                              void* d_out, int out_size) {
    const float* x    = (const float*)d_in[0];
    const int*   ei   = (const int*)d_in[1];
    const float* ea   = (const float*)d_in[2];
    const int*   bat  = (const int*)d_in[3];
    const float* clin = (const float*)d_in[4];
    const float* met  = (const float*)d_in[5];
    const float* W1   = (const float*)d_in[6];
    const float* as1  = (const float*)d_in[7];
    const float* ad1  = (const float*)d_in[8];
    const float* ae1  = (const float*)d_in[9];
    const float* We1  = (const float*)d_in[10];
    const float* b1   = (const float*)d_in[11];
    const float* W2   = (const float*)d_in[12];
    const float* as2  = (const float*)d_in[13];
    const float* ad2  = (const float*)d_in[14];
    const float* ae2  = (const float*)d_in[15];
    const float* We2  = (const float*)d_in[16];
    const float* b2   = (const float*)d_in[17];
    const float* lng  = (const float*)d_in[18];
    const float* lnb  = (const float*)d_in[19];
    const float* Wf1  = (const float*)d_in[20];
    const float* bf1  = (const float*)d_in[21];
    const float* Wf2  = (const float*)d_in[22];
    const float* bf2  = (const float*)d_in[23];
    const float* Wr   = (const float*)d_in[24];
    const float* br   = (const float*)d_in[25];
    float* out = (float*)d_out;

    // fork: CSR chain on side stream, GEMM(+logits) on main stream
    cudaStream_t s2;
    cudaEvent_t e0, e1;
    cudaStreamCreateWithFlags(&s2, cudaStreamNonBlocking);
    cudaEventCreateWithFlags(&e0, cudaEventDisableTiming);
    cudaEventCreateWithFlags(&e1, cudaEventDisableTiming);

    cudaEventRecord(e0, 0);
    cudaStreamWaitEvent(s2, e0, 0);

    prep_kernel<<<512, 256, 0, s2>>>(ea);                        // 0
    hist_kernel<<<(ELOOP + 255) / 256, 256, 0, s2>>>(ei);        // 1
    scan_kernel<<<1, 1024, 0, s2>>>(We1, ae1, We2, ae2);         // 2
    gemm1_kernel<<<dim3(C1 / 128, (NN + 127) / 128), 256>>>(x, W1, as1, ad1); // 3 (profiled)
    scatter_kernel<<<(ELOOP + 255) / 256, 256, 0, s2>>>(ei, ea); // 4
    cudaEventRecord(e1, s2);
    cudaStreamWaitEvent(0, e1, 0);

    // layer 1 aggregation (needs CSR + gemm1 logits)
    agg1_kernel<<<(NN * 32 + 255) / 256, 256>>>(b1);

    // layer 2 (gemm2 fuses logits2; g_als2/g_ald2 zeroed by prep)
    gemm2_kernel<<<dim3(1, (NN + 127) / 128), 256>>>(W2, as2, ad2);
    agg2_ln_pool_kernel<<<(NN * 32 + 255) / 256, 256>>>(b2, lng, lnb, bat);

    // head
    mlp_kernel<<<GG, 64>>>(clin, met, Wf1, bf1, Wf2, bf2, Wr, br, out);
    // streams/events intentionally not destroyed (graph may reference them)
}

// round 10
// speedup vs baseline: 6.0305x; 1.3118x over previous
#include <cuda_runtime.h>
#include <cuda_bf16.h>
#include <cstdint>

// ---------------- fixed problem shapes ----------------
#define NN      50000
#define EE      800000
#define ELOOP   850000        // EE + NN self loops
#define GG      64
#define FIN     128
#define HIDD    64
#define HEADS   4
#define C1      256           // HEADS*HIDD
#define CLIN    32
#define MET     128
#define FUSED_IN 224          // HID + CLIN + MET
#define NB      196           // ceil(NN/256) scan blocks

// ---------------- device scratch (no allocs allowed) ----------------
__device__ uint32_t g_h1b [(size_t)NN * (C1/2)];  // bf16x2 packed h1 (agg gather)
__device__ float    g_out1[(size_t)NN * C1];      // layer1 output (post bias+relu)
__device__ uint32_t g_h2b [(size_t)NN * (HIDD/2)];// bf16x2 packed h2
__device__ float g_als1[NN * HEADS];
__device__ float g_ald1[NN * HEADS];
__device__ float g_als2[NN];
__device__ float g_ald2[NN];
__device__ float g_sums[GG * HIDD];
__device__ float g_cnt [GG];
__device__ float g_scal[8];     // [0]=sum(edge_attr), [1..4]=ce1[h], [5]=ce2
__device__ float g_part[512];   // per-block partial sums of edge_attr
// CSR by destination
__device__ int  g_row [NN + 1];
__device__ int  g_cur [NN];     // hist -> degree -> cursor
__device__ int  g_bsum[256];    // per-scan-block degree sums
__device__ int  g_boff[256];    // exclusive block offsets
__device__ int2 g_elist[ELOOP]; // (src, float_bits(edge_attr)) sorted by dst

__device__ __forceinline__ uint32_t pack_bf16(float a, float b) {
    __nv_bfloat162 h = __float22bfloat162_rn(make_float2(a, b));
    return *reinterpret_cast<uint32_t*>(&h);
}
__device__ __forceinline__ float2 unpack_bf16(uint32_t u) {
    return __bfloat1622float2(*reinterpret_cast<__nv_bfloat162*>(&u));
}

// ---------------- prep: zero scratch + partial sums of edge_attr ----------------
__global__ void prep_kernel(const float* __restrict__ ea) {
    __shared__ float sh[8];
    int i = blockIdx.x * blockDim.x + threadIdx.x;
    if (i < NN) { g_cur[i] = 0; g_als2[i] = 0.f; g_ald2[i] = 0.f; }
    if (i < GG * HIDD) g_sums[i] = 0.f;
    if (i < GG) g_cnt[i] = 0.f;
    if (i < 8)  g_scal[i] = 0.f;
    float s = 0.f;
    for (size_t e = i; e < EE; e += (size_t)512 * 256) s += ea[e];
    for (int o = 16; o; o >>= 1) s += __shfl_xor_sync(0xffffffffu, s, o);
    if ((threadIdx.x & 31) == 0) sh[threadIdx.x >> 5] = s;
    __syncthreads();
    if (threadIdx.x < 8) {
        float v = sh[threadIdx.x];
        for (int o = 4; o; o >>= 1) v += __shfl_xor_sync(0xffu, v, o);
        if (threadIdx.x == 0) g_part[blockIdx.x] = v;
    }
}

// ---------------- CSR build: histogram of dst ----------------
__global__ void hist_kernel(const int* __restrict__ ei) {
    int e = blockIdx.x * blockDim.x + threadIdx.x;
    if (e >= ELOOP) return;
    int d = (e < EE) ? ei[EE + e] : (e - EE);
    atomicAdd(&g_cur[d], 1);
}

// ---------------- scan stage 1: per-block degree sums (NB blocks x 256) ----------------
__global__ void scan1_kernel() {
    __shared__ int sh[8];
    int idx = blockIdx.x * 256 + threadIdx.x;
    int v = (idx < NN) ? g_cur[idx] : 0;
    int s = v;
    for (int o = 16; o; o >>= 1) s += __shfl_xor_sync(0xffffffffu, s, o);
    if ((threadIdx.x & 31) == 0) sh[threadIdx.x >> 5] = s;
    __syncthreads();
    if (threadIdx.x < 8) {
        int u = sh[threadIdx.x];
        for (int o = 4; o; o >>= 1) u += __shfl_xor_sync(0xffu, u, o);
        if (threadIdx.x == 0) g_bsum[blockIdx.x] = u;
    }
}

// ---- scan stage 2 (1 block x 256): block-offset scan + mean finalize + ce dots ----
__global__ void scan2_kernel(const float* __restrict__ We1, const float* __restrict__ ae1,
                             const float* __restrict__ We2, const float* __restrict__ ae2) {
    __shared__ int ss[256];
    __shared__ float fs[8];
    int t = threadIdx.x;
    // finalize sum(edge_attr)
    float v = g_part[t] + g_part[t + 256];
    for (int o = 16; o; o >>= 1) v += __shfl_xor_sync(0xffffffffu, v, o);
    if ((t & 31) == 0) fs[t >> 5] = v;
    __syncthreads();
    if (t < 8) {
        float u = fs[t];
        for (int o = 4; o; o >>= 1) u += __shfl_xor_sync(0xffu, u, o);
        if (t == 0) g_scal[0] = u;
    }
    // ce dots
    atomicAdd(&g_scal[1 + (t >> 6)], We1[t] * ae1[t]);
    if (t < 64) atomicAdd(&g_scal[5], We2[t] * ae2[t]);
    // exclusive scan of NB block sums
    int b = (t < NB) ? g_bsum[t] : 0;
    ss[t] = b;
    __syncthreads();
    for (int off = 1; off < 256; off <<= 1) {
        int w = (t >= off) ? ss[t - off] : 0;
        __syncthreads();
        ss[t] += w;
        __syncthreads();
    }
    if (t < NB) g_boff[t] = ss[t] - b;
    if (t == 0) g_row[NN] = ELOOP;
}

// ---- scan stage 3: per-block exclusive scan + writeback (NB blocks x 256) ----
__global__ void scan3_kernel() {
    __shared__ int ss[256];
    int t = threadIdx.x;
    int idx = blockIdx.x * 256 + t;
    int d = (idx < NN) ? g_cur[idx] : 0;
    ss[t] = d;
    __syncthreads();
    for (int off = 1; off < 256; off <<= 1) {
        int w = (t >= off) ? ss[t - off] : 0;
        __syncthreads();
        ss[t] += w;
        __syncthreads();
    }
    int excl = ss[t] - d + g_boff[blockIdx.x];
    if (idx < NN) {
        g_row[idx] = excl;
        g_cur[idx] = excl;
    }
}

// ---------------- CSR build: scatter (src, edge_attr) ----------------
__global__ void scatter_kernel(const int* __restrict__ ei, const float* __restrict__ ea) {
    int e = blockIdx.x * blockDim.x + threadIdx.x;
    if (e >= ELOOP) return;
    int s, d; float att;
    if (e < EE) { s = ei[e]; d = ei[EE + e]; att = ea[e]; }
    else        { s = d = e - EE; att = g_scal[0] * (1.0f / EE); }
    int pos = atomicAdd(&g_cur[d], 1);
    g_elist[pos] = make_int2(s, __float_as_int(att));
}

// ---- TF32 GEMM, double-buffered, bf16 output + FUSED attention logits ----
template<int BN, int K, int LAYER>
__device__ __forceinline__ void gemm_tf32_body(const float* __restrict__ A,
                                               const float* __restrict__ B,
                                               uint32_t* __restrict__ Cb,
                                               const float* __restrict__ avS,
                                               const float* __restrict__ avD,
                                               int M, int Ncol) {
    constexpr int NF = BN / 16;
    __shared__ uint32_t As[2][128][20];
    __shared__ uint32_t Bs[2][16][BN + 8];
    int tid = threadIdx.x;
    int warp = tid >> 5, lane = tid & 31;
    int warp_m = warp & 3;
    int warp_n = warp >> 2;
    int m0 = blockIdx.y * 128, n0 = blockIdx.x * BN;
    int g = lane >> 2, t4 = lane & 3;

    int arow = tid >> 1, acb = (tid & 1) * 8;
    int brow = tid >> 4;
    int bcb  = (BN == 128) ? (tid & 15) * 8 : (tid & 15) * 4;

    float acc[2][NF][4];
#pragma unroll
    for (int mf = 0; mf < 2; mf++)
#pragma unroll
        for (int nf = 0; nf < NF; nf++)
#pragma unroll
            for (int i = 0; i < 4; i++) acc[mf][nf][i] = 0.f;

    float4 pa0, pa1, pb0, pb1;
    auto load_tile = [&](int k0) {
        pa0 = make_float4(0.f, 0.f, 0.f, 0.f);
        pa1 = make_float4(0.f, 0.f, 0.f, 0.f);
        if (m0 + arow < M) {
            const float* p = A + (size_t)(m0 + arow) * K + k0 + acb;
            pa0 = *(const float4*)p;
            pa1 = *(const float4*)(p + 4);
        }
        const float* q = B + (size_t)(k0 + brow) * Ncol + n0 + bcb;
        pb0 = *(const float4*)q;
        if (BN == 128) pb1 = *(const float4*)(q + 4);
    };
    auto store_tile = [&](int buf) {
        *(uint4*)&As[buf][arow][acb]     = *reinterpret_cast<uint4*>(&pa0);
        *(uint4*)&As[buf][arow][acb + 4] = *reinterpret_cast<uint4*>(&pa1);
        *(uint4*)&Bs[buf][brow][bcb]     = *reinterpret_cast<uint4*>(&pb0);
        if (BN == 128)
            *(uint4*)&Bs[buf][brow][bcb + 4] = *reinterpret_cast<uint4*>(&pb1);
    };
    auto compute = [&](int buf) {
#pragma unroll
        for (int ks = 0; ks < 16; ks += 8) {
            uint32_t a[2][4];
#pragma unroll
            for (int mf = 0; mf < 2; mf++) {
                int rb = warp_m * 32 + mf * 16;
                a[mf][0] = As[buf][rb + g][ks + t4];
                a[mf][1] = As[buf][rb + 8 + g][ks + t4];
                a[mf][2] = As[buf][rb + g][ks + 4 + t4];
                a[mf][3] = As[buf][rb + 8 + g][ks + 4 + t4];
            }
#pragma unroll
            for (int nf = 0; nf < NF; nf++) {
                int cb = warp_n * (BN / 2) + nf * 8;
                uint32_t b0 = Bs[buf][ks + t4][cb + g];
                uint32_t b1 = Bs[buf][ks + 4 + t4][cb + g];
#pragma unroll
                for (int mf = 0; mf < 2; mf++) {
                    asm volatile(
                        "mma.sync.aligned.m16n8k8.row.col.f32.tf32.tf32.f32 "
                        "{%0,%1,%2,%3}, {%4,%5,%6,%7}, {%8,%9}, {%0,%1,%2,%3};"
                        : "+f"(acc[mf][nf][0]), "+f"(acc[mf][nf][1]),
                          "+f"(acc[mf][nf][2]), "+f"(acc[mf][nf][3])
                        : "r"(a[mf][0]), "r"(a[mf][1]), "r"(a[mf][2]), "r"(a[mf][3]),
                          "r"(b0), "r"(b1));
                }
            }
        }
    };

    load_tile(0);
    store_tile(0);
    __syncthreads();
    int cur = 0;
    for (int k0 = 0; k0 < K; k0 += 16) {
        bool more = (k0 + 16 < K);
        if (more) load_tile(k0 + 16);
        compute(cur);
        if (more) store_tile(cur ^ 1);
        __syncthreads();
        cur ^= 1;
    }

    // ---- bf16 store ----
#pragma unroll
    for (int mf = 0; mf < 2; mf++) {
#pragma unroll
        for (int nf = 0; nf < NF; nf++) {
            int row0 = m0 + warp_m * 32 + mf * 16 + g;
            int col  = n0 + warp_n * (BN / 2) + nf * 8 + 2 * t4;
            if (row0 < M)
                Cb[(size_t)row0 * (Ncol / 2) + col / 2] = pack_bf16(acc[mf][nf][0], acc[mf][nf][1]);
            if (row0 + 8 < M)
                Cb[(size_t)(row0 + 8) * (Ncol / 2) + col / 2] = pack_bf16(acc[mf][nf][2], acc[mf][nf][3]);
        }
    }

    // ---- fused attention logits ----
    float2 wS[NF], wD[NF];
    int cbase = (LAYER == 1) ? ((blockIdx.x * 2 + warp_n) * 64) : (warp_n * (BN / 2));
#pragma unroll
    for (int nf = 0; nf < NF; nf++) {
        int c = cbase + nf * 8 + 2 * t4;
        wS[nf] = *(const float2*)(avS + c);
        wD[nf] = *(const float2*)(avD + c);
    }
#pragma unroll
    for (int mf = 0; mf < 2; mf++) {
        float ss0 = 0.f, dd0 = 0.f, ss1 = 0.f, dd1 = 0.f;
#pragma unroll
        for (int nf = 0; nf < NF; nf++) {
            ss0 += acc[mf][nf][0] * wS[nf].x + acc[mf][nf][1] * wS[nf].y;
            dd0 += acc[mf][nf][0] * wD[nf].x + acc[mf][nf][1] * wD[nf].y;
            ss1 += acc[mf][nf][2] * wS[nf].x + acc[mf][nf][3] * wS[nf].y;
            dd1 += acc[mf][nf][2] * wD[nf].x + acc[mf][nf][3] * wD[nf].y;
        }
        ss0 += __shfl_xor_sync(0xffffffffu, ss0, 1); ss0 += __shfl_xor_sync(0xffffffffu, ss0, 2);
        dd0 += __shfl_xor_sync(0xffffffffu, dd0, 1); dd0 += __shfl_xor_sync(0xffffffffu, dd0, 2);
        ss1 += __shfl_xor_sync(0xffffffffu, ss1, 1); ss1 += __shfl_xor_sync(0xffffffffu, ss1, 2);
        dd1 += __shfl_xor_sync(0xffffffffu, dd1, 1); dd1 += __shfl_xor_sync(0xffffffffu, dd1, 2);
        if (t4 == 0) {
            int row0 = m0 + warp_m * 32 + mf * 16 + g;
            if (LAYER == 1) {
                int head = blockIdx.x * 2 + warp_n;
                if (row0 < M)     { g_als1[row0 * 4 + head] = ss0; g_ald1[row0 * 4 + head] = dd0; }
                if (row0 + 8 < M) { g_als1[(row0 + 8) * 4 + head] = ss1; g_ald1[(row0 + 8) * 4 + head] = dd1; }
            } else {
                if (row0 < M)     { atomicAdd(&g_als2[row0], ss0); atomicAdd(&g_ald2[row0], dd0); }
                if (row0 + 8 < M) { atomicAdd(&g_als2[row0 + 8], ss1); atomicAdd(&g_ald2[row0 + 8], dd1); }
            }
        }
    }
}

__global__ void __launch_bounds__(256, 2)
gemm1_kernel(const float* __restrict__ x, const float* __restrict__ W1,
             const float* __restrict__ as1, const float* __restrict__ ad1) {
    gemm_tf32_body<128, FIN, 1>(x, W1, g_h1b, as1, ad1, NN, C1);
}
__global__ void __launch_bounds__(256, 2)
gemm2_kernel(const float* __restrict__ W2,
             const float* __restrict__ as2, const float* __restrict__ ad2) {
    gemm_tf32_body<64, C1, 2>(g_out1, W2, g_h2b, as2, ad2, NN, HIDD);
}

// ---- layer-1 aggregation: warp per dst node, phase-separated loads ----
__global__ void agg1_kernel(const float* __restrict__ b1) {
    int n = (blockIdx.x * blockDim.x + threadIdx.x) >> 5;
    int lane = threadIdx.x & 31;
    if (n >= NN) return;
    int beg = g_row[n], end = g_row[n + 1];
    int h = lane >> 3;
    float ald = g_ald1[n * 4 + h];
    float ce  = g_scal[1 + h];
    float4 acc0 = make_float4(0.f, 0.f, 0.f, 0.f);
    float4 acc1 = make_float4(0.f, 0.f, 0.f, 0.f);
    float den = 0.f;
    int j = beg;
    for (; j + 4 <= end; j += 4) {
        int2 se[4];
#pragma unroll
        for (int q = 0; q < 4; q++) se[q] = g_elist[j + q];
        uint4 p[4]; float al[4];
#pragma unroll
        for (int q = 0; q < 4; q++) {
            p[q]  = ((const uint4*)(g_h1b + (size_t)se[q].x * (C1 / 2)))[lane];
            al[q] = g_als1[se[q].x * 4 + h];
        }
        float ex[4];
#pragma unroll
        for (int q = 0; q < 4; q++) {
            float z = al[q] + ald + __int_as_float(se[q].y) * ce;
            z = z > 0.f ? z : 0.2f * z;
            ex[q] = __expf(z);
        }
#pragma unroll
        for (int q = 0; q < 4; q++) {
            float2 f0 = unpack_bf16(p[q].x), f1 = unpack_bf16(p[q].y);
            float2 f2 = unpack_bf16(p[q].z), f3 = unpack_bf16(p[q].w);
            den += ex[q];
            acc0.x += ex[q] * f0.x; acc0.y += ex[q] * f0.y;
            acc0.z += ex[q] * f1.x; acc0.w += ex[q] * f1.y;
            acc1.x += ex[q] * f2.x; acc1.y += ex[q] * f2.y;
            acc1.z += ex[q] * f3.x; acc1.w += ex[q] * f3.y;
        }
    }
    for (; j < end; j++) {
        int2 se = g_elist[j];
        uint4 p = ((const uint4*)(g_h1b + (size_t)se.x * (C1 / 2)))[lane];
        float z = g_als1[se.x * 4 + h] + ald + __int_as_float(se.y) * ce;
        z = z > 0.f ? z : 0.2f * z;
        float ex = __expf(z);
        float2 f0 = unpack_bf16(p.x), f1 = unpack_bf16(p.y);
        float2 f2 = unpack_bf16(p.z), f3 = unpack_bf16(p.w);
        den += ex;
        acc0.x += ex * f0.x; acc0.y += ex * f0.y;
        acc0.z += ex * f1.x; acc0.w += ex * f1.y;
        acc1.x += ex * f2.x; acc1.y += ex * f2.y;
        acc1.z += ex * f3.x; acc1.w += ex * f3.y;
    }
    float inv = 1.f / (den + 1e-16f);
    const float4* bp = (const float4*)b1;
    float4 bb0 = bp[lane * 2], bb1 = bp[lane * 2 + 1];
    float4 o0, o1;
    o0.x = fmaxf(acc0.x * inv + bb0.x, 0.f);
    o0.y = fmaxf(acc0.y * inv + bb0.y, 0.f);
    o0.z = fmaxf(acc0.z * inv + bb0.z, 0.f);
    o0.w = fmaxf(acc0.w * inv + bb0.w, 0.f);
    o1.x = fmaxf(acc1.x * inv + bb1.x, 0.f);
    o1.y = fmaxf(acc1.y * inv + bb1.y, 0.f);
    o1.z = fmaxf(acc1.z * inv + bb1.z, 0.f);
    o1.w = fmaxf(acc1.w * inv + bb1.w, 0.f);
    float4* op = (float4*)(g_out1 + (size_t)n * C1);
    op[lane * 2] = o0;
    op[lane * 2 + 1] = o1;
}

// ---- layer-2 aggregation (bf16 gather) + bias + LayerNorm + pool ----
__global__ void agg2_ln_pool_kernel(const float* __restrict__ b2,
                                    const float* __restrict__ lng,
                                    const float* __restrict__ lnb,
                                    const int* __restrict__ batch) {
    int n = (blockIdx.x * blockDim.x + threadIdx.x) >> 5;
    int lane = threadIdx.x & 31;
    if (n >= NN) return;
    int beg = g_row[n], end = g_row[n + 1];
    float ald = g_ald2[n];
    float ce  = g_scal[5];
    float2 acc = make_float2(0.f, 0.f);
    float den = 0.f;
    int j = beg;
    for (; j + 4 <= end; j += 4) {
        int2 se[4];
#pragma unroll
        for (int q = 0; q < 4; q++) se[q] = g_elist[j + q];
        uint32_t p[4]; float al[4];
#pragma unroll
        for (int q = 0; q < 4; q++) {
            p[q]  = (g_h2b + (size_t)se[q].x * (HIDD / 2))[lane];
            al[q] = g_als2[se[q].x];
        }
        float ex[4];
#pragma unroll
        for (int q = 0; q < 4; q++) {
            float z = al[q] + ald + __int_as_float(se[q].y) * ce;
            z = z > 0.f ? z : 0.2f * z;
            ex[q] = __expf(z);
        }
#pragma unroll
        for (int q = 0; q < 4; q++) {
            float2 f = unpack_bf16(p[q]);
            den += ex[q];
            acc.x += ex[q] * f.x;
            acc.y += ex[q] * f.y;
        }
    }
    for (; j < end; j++) {
        int2 se = g_elist[j];
        uint32_t p = (g_h2b + (size_t)se.x * (HIDD / 2))[lane];
        float z = g_als2[se.x] + ald + __int_as_float(se.y) * ce;
        z = z > 0.f ? z : 0.2f * z;
        float ex = __expf(z);
        float2 f = unpack_bf16(p);
        den += ex;
        acc.x += ex * f.x;
        acc.y += ex * f.y;
    }
    float inv = 1.f / (den + 1e-16f);
    float2 bb = ((const float2*)b2)[lane];
    float vx = acc.x * inv + bb.x;
    float vy = acc.y * inv + bb.y;
    float s = vx + vy;
    for (int o = 16; o; o >>= 1) s += __shfl_xor_sync(0xffffffffu, s, o);
    float mu = s * (1.0f / 64.0f);
    float dx = vx - mu, dy = vy - mu;
    float q = dx * dx + dy * dy;
    for (int o = 16; o; o >>= 1) q += __shfl_xor_sync(0xffffffffu, q, o);
    float r = rsqrtf(q * (1.0f / 64.0f) + 1e-5f);
    float y0 = dx * r * lng[lane * 2]     + lnb[lane * 2];
    float y1 = dy * r * lng[lane * 2 + 1] + lnb[lane * 2 + 1];
    int g = batch[n];
    atomicAdd(&g_sums[g * 64 + lane * 2],     y0);
    atomicAdd(&g_sums[g * 64 + lane * 2 + 1], y1);
    if (lane == 0) atomicAdd(&g_cnt[g], 1.0f);
}

// ---------------- per-graph MLP head (block per graph, 64 threads) ----------------
__global__ void mlp_kernel(const float* __restrict__ clin, const float* __restrict__ met,
                           const float* __restrict__ Wf1, const float* __restrict__ bf1,
                           const float* __restrict__ Wf2, const float* __restrict__ bf2,
                           const float* __restrict__ Wr,  const float* __restrict__ br,
                           float* __restrict__ out) {
    int g = blockIdx.x, t = threadIdx.x;   // 64 threads
    __shared__ float fused[FUSED_IN];
    __shared__ float l1[64];
    __shared__ float l2[32];
    float cnt = g_cnt[g]; cnt = cnt > 1.f ? cnt : 1.f;
    float e = g_sums[g * 64 + t] / cnt;
    fused[t] = e;
    out[GG + g * 64 + t] = e;              // graph_embedding at offset 64
    if (t < 32) fused[64 + t] = clin[g * 32 + t];
    fused[96 + t]  = met[g * 128 + t];
    fused[160 + t] = met[g * 128 + 64 + t];
    __syncthreads();
    float acc = bf1[t];
#pragma unroll 8
    for (int k = 0; k < FUSED_IN; k++) acc += fused[k] * Wf1[k * 64 + t];
    l1[t] = acc > 0.f ? acc : 0.f;
    __syncthreads();
    if (t < 32) {
        float a2 = bf2[t];
#pragma unroll 8
        for (int j = 0; j < 64; j++) a2 += l1[j] * Wf2[j * 32 + t];
        a2 = a2 > 0.f ? a2 : 0.f;
        l2[t] = a2;
        out[GG + GG * 64 + g * 32 + t] = a2;   // latent at offset 64 + 4096
    }
    __syncthreads();
    if (t == 0) {
        float r = br[0];
#pragma unroll
        for (int j = 0; j < 32; j++) r += l2[j] * Wr[j];
        out[g] = r;                        // risk at offset 0
    }
}

// ---------------- launch ----------------
extern "C" void kernel_launch(void* const* d_in, const int* in_sizes, int n_in,
                              void* d_out, int out_size) {
    const float* x    = (const float*)d_in[0];
    const int*   ei   = (const int*)d_in[1];
    const float* ea   = (const float*)d_in[2];
    const int*   bat  = (const int*)d_in[3];
    const float* clin = (const float*)d_in[4];
    const float* met  = (const float*)d_in[5];
    const float* W1   = (const float*)d_in[6];
    const float* as1  = (const float*)d_in[7];
    const float* ad1  = (const float*)d_in[8];
    const float* ae1  = (const float*)d_in[9];
    const float* We1  = (const float*)d_in[10];
    const float* b1   = (const float*)d_in[11];
    const float* W2   = (const float*)d_in[12];
    const float* as2  = (const float*)d_in[13];
    const float* ad2  = (const float*)d_in[14];
    const float* ae2  = (const float*)d_in[15];
    const float* We2  = (const float*)d_in[16];
    const float* b2   = (const float*)d_in[17];
    const float* lng  = (const float*)d_in[18];
    const float* lnb  = (const float*)d_in[19];
    const float* Wf1  = (const float*)d_in[20];
    const float* bf1  = (const float*)d_in[21];
    const float* Wf2  = (const float*)d_in[22];
    const float* bf2  = (const float*)d_in[23];
    const float* Wr   = (const float*)d_in[24];
    const float* br   = (const float*)d_in[25];
    float* out = (float*)d_out;

    // fork: CSR chain on side stream, GEMM(+logits) on main stream
    cudaStream_t s2;
    cudaEvent_t e0, e1;
    cudaStreamCreateWithFlags(&s2, cudaStreamNonBlocking);
    cudaEventCreateWithFlags(&e0, cudaEventDisableTiming);
    cudaEventCreateWithFlags(&e1, cudaEventDisableTiming);

    cudaEventRecord(e0, 0);
    cudaStreamWaitEvent(s2, e0, 0);

    prep_kernel<<<512, 256, 0, s2>>>(ea);                        // 0
    hist_kernel<<<(ELOOP + 255) / 256, 256, 0, s2>>>(ei);        // 1
    scan1_kernel<<<NB, 256, 0, s2>>>();                          // 2
    gemm1_kernel<<<dim3(C1 / 128, (NN + 127) / 128), 256>>>(x, W1, as1, ad1); // 3 (profiled)
    scan2_kernel<<<1, 256, 0, s2>>>(We1, ae1, We2, ae2);         // 4
    scan3_kernel<<<NB, 256, 0, s2>>>();                          // 5
    scatter_kernel<<<(ELOOP + 255) / 256, 256, 0, s2>>>(ei, ea); // 6
    cudaEventRecord(e1, s2);
    cudaStreamWaitEvent(0, e1, 0);

    // layer 1 aggregation (needs CSR + gemm1 logits)
    agg1_kernel<<<(NN * 32 + 255) / 256, 256>>>(b1);

    // layer 2 (gemm2 fuses logits2; g_als2/g_ald2 zeroed by prep)
    gemm2_kernel<<<dim3(1, (NN + 127) / 128), 256>>>(W2, as2, ad2);
    agg2_ln_pool_kernel<<<(NN * 32 + 255) / 256, 256>>>(b2, lng, lnb, bat);

    // head
    mlp_kernel<<<GG, 64>>>(clin, met, Wf1, bf1, Wf2, bf2, Wr, br, out);
    // streams/events intentionally not destroyed (graph may reference them)
}